// round 12
// baseline (speedup 1.0000x reference)
#include <cuda_runtime.h>
#include <cuda_fp16.h>
#include <cuda_bf16.h>
#include <math.h>
#include <stdint.h>

// ---------------------------------------------------------------------------
// Model dims
// ---------------------------------------------------------------------------
#define SEQ    64
#define TLEN   256
#define FDIM   256
#define NHEAD  8
#define HDIM   32
#define MROWS  16384
#define EDIM   1024
#define DFLAT  262144
#define NB     16
#define NLAYER 6

// ---------------------------------------------------------------------------
// Scratch
// ---------------------------------------------------------------------------
__device__ float  g_h   [SEQ*TLEN*FDIM];
__device__ float  g_x1  [SEQ*TLEN*FDIM];
__device__ float  g_flat[NB*DFLAT];
__device__ float  g_z1p [2*256*NB*64];
__device__ float  g_z1  [2*256*NB];
__device__ __align__(256) __half g_attnh[SEQ*TLEN*FDIM];
__device__ __align__(256) __half g_x1h  [SEQ*TLEN*FDIM];
__device__ __align__(256) __half g_ffh  [MROWS*EDIM];
__device__ __align__(256) __half g_Woh  [NLAYER*FDIM*FDIM];
__device__ __align__(256) __half g_W1h  [NLAYER*EDIM*FDIM];
__device__ __align__(256) __half g_W2h  [NLAYER*FDIM*EDIM];

// ---------------------------------------------------------------------------
// fp32 -> fp16 weight conversion
// ---------------------------------------------------------------------------
__global__ void k_cvt(const float* __restrict__ s, __half* __restrict__ d, int n) {
    int i = blockIdx.x * 256 + threadIdx.x;
    if (i < n) d[i] = __float2half_rn(s[i]);
}

// ---------------------------------------------------------------------------
// Embed (smem transpose, coalesced both sides)
// ---------------------------------------------------------------------------
__global__ __launch_bounds__(256) void k_embed2(
    const float* __restrict__ x, float* __restrict__ h)
{
    __shared__ float sm[4][32][33];
    int f0 = blockIdx.x * 32;
    int t0 = blockIdx.y * 32;
    int n  = blockIdx.z;
    int tid = threadIdx.x;
    int ti = tid & 31;
    int w8 = tid >> 5;

    #pragma unroll
    for (int i = 0; i < 4; i++) {
        int fi = w8 * 4 + i;
        float4 v = *(const float4*)(x + ((((size_t)n*256 + f0 + fi)*256 + t0 + ti) << 2));
        sm[0][ti][fi] = v.x;
        sm[1][ti][fi] = v.y;
        sm[2][ti][fi] = v.z;
        sm[3][ti][fi] = v.w;
    }
    __syncthreads();

    int fi = tid & 31;
    #pragma unroll
    for (int c = 0; c < 4; c++) {
        #pragma unroll
        for (int tt = 0; tt < 4; tt++) {
            int tiw = w8 * 4 + tt;
            int t = t0 + tiw;
            h[((size_t)(c*16 + n)*256 + t)*256 + f0 + fi] =
                sm[c][tiw][fi] + (float)t * (1.0f/255.0f);
        }
    }
}

// ---------------------------------------------------------------------------
// MMA helpers
// ---------------------------------------------------------------------------
#define MMA_TF32(C, A0, A1, A2, A3, B0, B1) \
    asm volatile( \
        "mma.sync.aligned.m16n8k8.row.col.f32.tf32.tf32.f32 " \
        "{%0,%1,%2,%3}, {%4,%5,%6,%7}, {%8,%9}, {%0,%1,%2,%3};\n" \
        : "+f"((C)[0]), "+f"((C)[1]), "+f"((C)[2]), "+f"((C)[3]) \
        : "r"(A0), "r"(A1), "r"(A2), "r"(A3), "r"(B0), "r"(B1))

#define MMA_F16(C, A0, A1, A2, A3, B0, B1) \
    asm volatile( \
        "mma.sync.aligned.m16n8k16.row.col.f32.f16.f16.f32 " \
        "{%0,%1,%2,%3}, {%4,%5,%6,%7}, {%8,%9}, {%0,%1,%2,%3};\n" \
        : "+f"((C)[0]), "+f"((C)[1]), "+f"((C)[2]), "+f"((C)[3]) \
        : "r"(A0), "r"(A1), "r"(A2), "r"(A3), "r"(B0), "r"(B1))

__device__ __forceinline__ void cpasync16(void* sdst, const void* gsrc) {
    unsigned int s = (unsigned int)__cvta_generic_to_shared(sdst);
    asm volatile("cp.async.cg.shared.global [%0], [%1], 16;\n" :: "r"(s), "l"(gsrc));
}
__device__ __forceinline__ unsigned int tf32_hi(float a) {
    unsigned int h;
    asm("cvt.rna.tf32.f32 %0, %1;" : "=r"(h) : "f"(a));
    return h;
}

// ---------------------------------------------------------------------------
// fp16 GEMM (relu, fp16 out): CTA 256x128, 8 warps of 64x64, BK=32, 3-stage.
// out[m][n] = relu(sum_k A[m][k]*B[n][k] + bias[n]).  K in elements.
// ---------------------------------------------------------------------------
#define HP 40                       // halves per smem row (80B, 16B-mult)
#define F1_ASZ (256*HP)
#define F1_BSZ (128*HP)
#define F1_SMEM ((3*(F1_ASZ + F1_BSZ))*2)

__global__ __launch_bounds__(256, 1) void k_gemm_f16(
    const __half* __restrict__ A, const __half* __restrict__ B,
    const float* __restrict__ bias, __half* __restrict__ out,
    int N, int K)
{
    extern __shared__ __half smh16[];
    __half* Asm = smh16;
    __half* Bsm = smh16 + 3*F1_ASZ;
    int bm = blockIdx.x * 256, bn = blockIdx.y * 128;
    int tid = threadIdx.x;
    int lane = tid & 31;
    int wid  = tid >> 5;
    int gid  = lane >> 2, tig = lane & 3;
    int wm = (wid >> 1) * 64;
    int wn = (wid & 1) * 64;

    float c[4][8][4];
    #pragma unroll
    for (int mt = 0; mt < 4; mt++)
        #pragma unroll
        for (int nt = 0; nt < 8; nt++)
            #pragma unroll
            for (int i = 0; i < 4; i++) c[mt][nt][i] = 0.f;

    int KT = K >> 5;

    auto issue = [&](int st, int kb) {
        __half* as = Asm + st*F1_ASZ;
        #pragma unroll
        for (int i = 0; i < 4; i++) {           // 256 rows x 4 chunks
            int idx = tid + i*256;
            int r = idx >> 2, ch = idx & 3;
            cpasync16(as + r*HP + ch*8, A + (size_t)(bm + r)*K + kb*32 + ch*8);
        }
        __half* bs = Bsm + st*F1_BSZ;
        #pragma unroll
        for (int i = 0; i < 2; i++) {           // 128 rows x 4 chunks
            int idx = tid + i*256;
            int r = idx >> 2, ch = idx & 3;
            cpasync16(bs + r*HP + ch*8, B + (size_t)(bn + r)*K + kb*32 + ch*8);
        }
        asm volatile("cp.async.commit_group;\n");
    };

    issue(0, 0);
    issue(1, 1);
    int issued = 2;
    int st = 0, stn = 2;

    for (int kb = 0; kb < KT; kb++) {
        if (issued - kb - 1 >= 1) asm volatile("cp.async.wait_group 1;\n");
        else                      asm volatile("cp.async.wait_group 0;\n");
        __syncthreads();

        const __half* as = Asm + st*F1_ASZ;
        const __half* bs = Bsm + st*F1_BSZ;
        #pragma unroll
        for (int ks = 0; ks < 2; ks++) {
            int k0 = ks * 16;
            unsigned int a[4][4];
            #pragma unroll
            for (int mt = 0; mt < 4; mt++) {
                int mr = wm + mt*16 + gid;
                a[mt][0] = *(const unsigned int*)&as[mr*HP + k0 + 2*tig];
                a[mt][1] = *(const unsigned int*)&as[(mr+8)*HP + k0 + 2*tig];
                a[mt][2] = *(const unsigned int*)&as[mr*HP + k0 + 2*tig + 8];
                a[mt][3] = *(const unsigned int*)&as[(mr+8)*HP + k0 + 2*tig + 8];
            }
            unsigned int b[8][2];
            #pragma unroll
            for (int nt = 0; nt < 8; nt++) {
                int nc = wn + nt*8 + gid;
                b[nt][0] = *(const unsigned int*)&bs[nc*HP + k0 + 2*tig];
                b[nt][1] = *(const unsigned int*)&bs[nc*HP + k0 + 2*tig + 8];
            }
            #pragma unroll
            for (int mt = 0; mt < 4; mt++)
                #pragma unroll
                for (int nt = 0; nt < 8; nt++)
                    MMA_F16(c[mt][nt], a[mt][0], a[mt][1], a[mt][2], a[mt][3],
                            b[nt][0], b[nt][1]);
        }

        if (kb + 2 < KT) { issue(stn, kb + 2); issued++; }
        st  = (st  == 2) ? 0 : st  + 1;
        stn = (stn == 2) ? 0 : stn + 1;
    }

    #pragma unroll
    for (int mt = 0; mt < 4; mt++) {
        #pragma unroll
        for (int nt = 0; nt < 8; nt++) {
            int col = bn + wn + nt*8 + (tig << 1);
            float bx = bias[col], by = bias[col + 1];
            #pragma unroll
            for (int hf = 0; hf < 2; hf++) {
                int row = bm + wm + mt*16 + gid + hf*8;
                float v0 = fmaxf(c[mt][nt][hf*2 + 0] + bx, 0.f);
                float v1 = fmaxf(c[mt][nt][hf*2 + 1] + by, 0.f);
                *(__half2*)(out + (size_t)row*N + col) = __floats2half2_rn(v0, v1);
            }
        }
    }
}

// ---------------------------------------------------------------------------
// fp16 GEMM + fused bias + fp32 residual + LayerNorm. N = 256 fixed.
// CTA 128x256 (full rows), 8 warps of 32x128, BK=32, 3-stage.
// out fp32; optional out2 fp16 copy.
// ---------------------------------------------------------------------------
#define GL_ASZ (128*HP)
#define GL_BSZ (256*HP)
#define GL_SMEM ((3*(GL_ASZ + GL_BSZ))*2)

__global__ __launch_bounds__(256, 1) void k_gemm_lnf(
    const __half* __restrict__ A, const __half* __restrict__ B,
    const float* __restrict__ bias, const float* __restrict__ resid,
    const float* __restrict__ lng, const float* __restrict__ lnb,
    float* __restrict__ out, __half* __restrict__ out2, int K)
{
    extern __shared__ __half smh16[];
    __half* Asm = smh16;
    __half* Bsm = smh16 + 3*GL_ASZ;
    float* smf = (float*)smh16;
    int bm = blockIdx.x * 128;
    int tid = threadIdx.x;
    int lane = tid & 31;
    int wid  = tid >> 5;
    int gid  = lane >> 2, tig = lane & 3;
    int wm = (wid >> 1) * 32;
    int wn = (wid & 1) * 128;

    float c[2][16][4];
    #pragma unroll
    for (int mt = 0; mt < 2; mt++)
        #pragma unroll
        for (int nt = 0; nt < 16; nt++)
            #pragma unroll
            for (int i = 0; i < 4; i++) c[mt][nt][i] = 0.f;

    int KT = K >> 5;

    auto issue = [&](int st, int kb) {
        __half* as = Asm + st*GL_ASZ;
        #pragma unroll
        for (int i = 0; i < 2; i++) {           // 128 rows x 4 chunks
            int idx = tid + i*256;
            int r = idx >> 2, ch = idx & 3;
            cpasync16(as + r*HP + ch*8, A + (size_t)(bm + r)*K + kb*32 + ch*8);
        }
        __half* bs = Bsm + st*GL_BSZ;
        #pragma unroll
        for (int i = 0; i < 4; i++) {           // 256 rows x 4 chunks
            int idx = tid + i*256;
            int r = idx >> 2, ch = idx & 3;
            cpasync16(bs + r*HP + ch*8, B + (size_t)r*K + kb*32 + ch*8);
        }
        asm volatile("cp.async.commit_group;\n");
    };

    issue(0, 0);
    issue(1, 1);
    int issued = 2;
    int st = 0, stn = 2;

    for (int kb = 0; kb < KT; kb++) {
        if (issued - kb - 1 >= 1) asm volatile("cp.async.wait_group 1;\n");
        else                      asm volatile("cp.async.wait_group 0;\n");
        __syncthreads();

        const __half* as = Asm + st*GL_ASZ;
        const __half* bs = Bsm + st*GL_BSZ;
        #pragma unroll
        for (int ks = 0; ks < 2; ks++) {
            int k0 = ks * 16;
            unsigned int a[2][4];
            #pragma unroll
            for (int mt = 0; mt < 2; mt++) {
                int mr = wm + mt*16 + gid;
                a[mt][0] = *(const unsigned int*)&as[mr*HP + k0 + 2*tig];
                a[mt][1] = *(const unsigned int*)&as[(mr+8)*HP + k0 + 2*tig];
                a[mt][2] = *(const unsigned int*)&as[mr*HP + k0 + 2*tig + 8];
                a[mt][3] = *(const unsigned int*)&as[(mr+8)*HP + k0 + 2*tig + 8];
            }
            #pragma unroll
            for (int nt = 0; nt < 16; nt++) {
                int nc = wn + nt*8 + gid;
                unsigned int b0 = *(const unsigned int*)&bs[nc*HP + k0 + 2*tig];
                unsigned int b1 = *(const unsigned int*)&bs[nc*HP + k0 + 2*tig + 8];
                #pragma unroll
                for (int mt = 0; mt < 2; mt++)
                    MMA_F16(c[mt][nt], a[mt][0], a[mt][1], a[mt][2], a[mt][3], b0, b1);
            }
        }

        if (kb + 2 < KT) { issue(stn, kb + 2); issued++; }
        st  = (st  == 2) ? 0 : st  + 1;
        stn = (stn == 2) ? 0 : stn + 1;
    }

    // ---- fused epilogue: bias + resid, LayerNorm over 256 cols ----
    __syncthreads();
    float* red1 = smf;
    float* red2 = smf + 256;

    #pragma unroll
    for (int mt = 0; mt < 2; mt++)
        #pragma unroll
        for (int nt = 0; nt < 16; nt++) {
            int col = wn + nt*8 + (tig << 1);
            float bx = bias[col], by = bias[col + 1];
            #pragma unroll
            for (int hf = 0; hf < 2; hf++) {
                int row = bm + wm + mt*16 + gid + hf*8;
                float2 r2 = *(const float2*)(resid + (size_t)row*256 + col);
                c[mt][nt][hf*2 + 0] += bx + r2.x;
                c[mt][nt][hf*2 + 1] += by + r2.y;
            }
        }

    #pragma unroll
    for (int mt = 0; mt < 2; mt++)
        #pragma unroll
        for (int hf = 0; hf < 2; hf++) {
            float s = 0.f;
            #pragma unroll
            for (int nt = 0; nt < 16; nt++)
                s += c[mt][nt][hf*2] + c[mt][nt][hf*2 + 1];
            s += __shfl_xor_sync(0xffffffffu, s, 1);
            s += __shfl_xor_sync(0xffffffffu, s, 2);
            if (tig == 0) {
                int r = wm + mt*16 + gid + hf*8;
                red1[(wid & 1)*128 + r] = s;
            }
        }
    __syncthreads();
    float mean[2][2];
    #pragma unroll
    for (int mt = 0; mt < 2; mt++)
        #pragma unroll
        for (int hf = 0; hf < 2; hf++) {
            int r = wm + mt*16 + gid + hf*8;
            mean[mt][hf] = (red1[r] + red1[128 + r]) * (1.f/256.f);
        }

    #pragma unroll
    for (int mt = 0; mt < 2; mt++)
        #pragma unroll
        for (int hf = 0; hf < 2; hf++) {
            float m = mean[mt][hf];
            float sq = 0.f;
            #pragma unroll
            for (int nt = 0; nt < 16; nt++) {
                float d0 = c[mt][nt][hf*2] - m;
                float d1 = c[mt][nt][hf*2 + 1] - m;
                sq += d0*d0 + d1*d1;
            }
            sq += __shfl_xor_sync(0xffffffffu, sq, 1);
            sq += __shfl_xor_sync(0xffffffffu, sq, 2);
            if (tig == 0) {
                int r = wm + mt*16 + gid + hf*8;
                red2[(wid & 1)*128 + r] = sq;
            }
        }
    __syncthreads();
    float rstd[2][2];
    #pragma unroll
    for (int mt = 0; mt < 2; mt++)
        #pragma unroll
        for (int hf = 0; hf < 2; hf++) {
            int r = wm + mt*16 + gid + hf*8;
            rstd[mt][hf] = rsqrtf((red2[r] + red2[128 + r]) * (1.f/256.f) + 1e-5f);
        }

    #pragma unroll
    for (int mt = 0; mt < 2; mt++)
        #pragma unroll
        for (int nt = 0; nt < 16; nt++) {
            int col = wn + nt*8 + (tig << 1);
            float2 gg = *(const float2*)(lng + col);
            float2 bb = *(const float2*)(lnb + col);
            #pragma unroll
            for (int hf = 0; hf < 2; hf++) {
                int row = bm + wm + mt*16 + gid + hf*8;
                float m = mean[mt][hf], rs = rstd[mt][hf];
                float v0 = (c[mt][nt][hf*2]     - m) * rs * gg.x + bb.x;
                float v1 = (c[mt][nt][hf*2 + 1] - m) * rs * gg.y + bb.y;
                *(float2*)(out + (size_t)row*256 + col) = make_float2(v0, v1);
                if (out2)
                    *(__half2*)(out2 + (size_t)row*256 + col) = __floats2half2_rn(v0, v1);
            }
        }
}

// ---------------------------------------------------------------------------
// Tensor-core attention (tf32 mma), fp16 output. One block per (seq, head).
// ---------------------------------------------------------------------------
#define ZP 36
#define VP 40
#define ATTN_SMEM ((3*256*ZP + 256*VP + 96*36) * 4)

__global__ __launch_bounds__(256, 1) void k_attn_tc(
    const float* __restrict__ h, const float* __restrict__ Wq,
    const float* __restrict__ Wk, const float* __restrict__ Wv,
    __half* __restrict__ out)
{
    int s  = blockIdx.x;
    int hh = blockIdx.y;
    extern __shared__ float sma[];
    float* Z  = sma;
    float* Qs = sma + 256*ZP;
    float* Ks = sma + 2*256*ZP;
    float* Vs = sma + 3*256*ZP;
    float* Ws = sma + 3*256*ZP + 256*VP;

    int tid  = threadIdx.x;
    int lane = tid & 31;
    int wid  = tid >> 5;
    int gid  = lane >> 2, tig = lane & 3;
    int m0   = wid * 32;

    for (int i = tid; i < 1024; i += 256) {
        int r = i >> 5, c2 = i & 31;
        Ws[r*36 + c2]        = Wq[i];
        Ws[(32 + r)*36 + c2] = Wk[i];
        Ws[(64 + r)*36 + c2] = Wv[i];
    }
    {
        const float4* hrow = (const float4*)(h + ((size_t)s*TLEN + tid)*FDIM + hh*HDIM);
        #pragma unroll
        for (int i4 = 0; i4 < 8; i4++)
            *(float4*)&Z[tid*ZP + i4*4] = hrow[i4];
    }
    __syncthreads();

    {
        float aq[2][4][4], ak[2][4][4], av[2][4][4];
        #pragma unroll
        for (int mt = 0; mt < 2; mt++)
            #pragma unroll
            for (int nt = 0; nt < 4; nt++)
                #pragma unroll
                for (int i = 0; i < 4; i++) { aq[mt][nt][i]=0.f; ak[mt][nt][i]=0.f; av[mt][nt][i]=0.f; }

        #pragma unroll
        for (int ks = 0; ks < 4; ks++) {
            int k0 = ks * 8;
            unsigned int a[2][4];
            #pragma unroll
            for (int mt = 0; mt < 2; mt++) {
                int mr = m0 + mt*16 + gid;
                a[mt][0] = __float_as_uint(Z[mr*ZP + k0 + tig]);
                a[mt][1] = __float_as_uint(Z[(mr+8)*ZP + k0 + tig]);
                a[mt][2] = __float_as_uint(Z[mr*ZP + k0 + tig + 4]);
                a[mt][3] = __float_as_uint(Z[(mr+8)*ZP + k0 + tig + 4]);
            }
            #pragma unroll
            for (int nt = 0; nt < 4; nt++) {
                int nc = nt*8 + gid;
                unsigned int bq0 = __float_as_uint(Ws[nc*36 + k0 + tig]);
                unsigned int bq1 = __float_as_uint(Ws[nc*36 + k0 + tig + 4]);
                unsigned int bk0 = __float_as_uint(Ws[(32+nc)*36 + k0 + tig]);
                unsigned int bk1 = __float_as_uint(Ws[(32+nc)*36 + k0 + tig + 4]);
                unsigned int bv0 = __float_as_uint(Ws[(64+nc)*36 + k0 + tig]);
                unsigned int bv1 = __float_as_uint(Ws[(64+nc)*36 + k0 + tig + 4]);
                #pragma unroll
                for (int mt = 0; mt < 2; mt++) {
                    MMA_TF32(aq[mt][nt], a[mt][0], a[mt][1], a[mt][2], a[mt][3], bq0, bq1);
                    MMA_TF32(ak[mt][nt], a[mt][0], a[mt][1], a[mt][2], a[mt][3], bk0, bk1);
                    MMA_TF32(av[mt][nt], a[mt][0], a[mt][1], a[mt][2], a[mt][3], bv0, bv1);
                }
            }
        }
        #pragma unroll
        for (int mt = 0; mt < 2; mt++)
            #pragma unroll
            for (int nt = 0; nt < 4; nt++) {
                int col = nt*8 + tig*2;
                #pragma unroll
                for (int hf = 0; hf < 2; hf++) {
                    int rowq = m0 + mt*16 + gid + hf*8;
                    *(float2*)&Qs[rowq*ZP + col] = make_float2(aq[mt][nt][hf*2], aq[mt][nt][hf*2+1]);
                    *(float2*)&Ks[rowq*ZP + col] = make_float2(ak[mt][nt][hf*2], ak[mt][nt][hf*2+1]);
                    *(float2*)&Vs[rowq*VP + col] = make_float2(av[mt][nt][hf*2], av[mt][nt][hf*2+1]);
                }
            }
    }
    __syncthreads();

    float* Pw = Z + m0*ZP;
    float o_acc[2][4][4];
    float lsum[2][2];
    #pragma unroll
    for (int mt = 0; mt < 2; mt++) {
        lsum[mt][0] = 0.f; lsum[mt][1] = 0.f;
        #pragma unroll
        for (int nt = 0; nt < 4; nt++)
            #pragma unroll
            for (int i = 0; i < 4; i++) o_acc[mt][nt][i] = 0.f;
    }

    for (int jc = 0; jc < 4; jc++) {
        float s_acc[2][8][4];
        #pragma unroll
        for (int mt = 0; mt < 2; mt++)
            #pragma unroll
            for (int nt = 0; nt < 8; nt++)
                #pragma unroll
                for (int i = 0; i < 4; i++) s_acc[mt][nt][i] = 0.f;

        #pragma unroll
        for (int ks = 0; ks < 4; ks++) {
            int k0 = ks * 8;
            unsigned int a[2][4];
            #pragma unroll
            for (int mt = 0; mt < 2; mt++) {
                int mr = m0 + mt*16 + gid;
                a[mt][0] = __float_as_uint(Qs[mr*ZP + k0 + tig]);
                a[mt][1] = __float_as_uint(Qs[(mr+8)*ZP + k0 + tig]);
                a[mt][2] = __float_as_uint(Qs[mr*ZP + k0 + tig + 4]);
                a[mt][3] = __float_as_uint(Qs[(mr+8)*ZP + k0 + tig + 4]);
            }
            #pragma unroll
            for (int nt = 0; nt < 8; nt++) {
                int nc = jc*64 + nt*8 + gid;
                unsigned int b0 = __float_as_uint(Ks[nc*ZP + k0 + tig]);
                unsigned int b1 = __float_as_uint(Ks[nc*ZP + k0 + tig + 4]);
                #pragma unroll
                for (int mt = 0; mt < 2; mt++)
                    MMA_TF32(s_acc[mt][nt], a[mt][0], a[mt][1], a[mt][2], a[mt][3], b0, b1);
            }
        }
        #pragma unroll
        for (int mt = 0; mt < 2; mt++)
            #pragma unroll
            for (int nt = 0; nt < 8; nt++) {
                float p0 = __expf(s_acc[mt][nt][0] * 0.0625f);
                float p1 = __expf(s_acc[mt][nt][1] * 0.0625f);
                float p2 = __expf(s_acc[mt][nt][2] * 0.0625f);
                float p3 = __expf(s_acc[mt][nt][3] * 0.0625f);
                lsum[mt][0] += p0 + p1;
                lsum[mt][1] += p2 + p3;
                int col = nt*8 + tig*2;
                int lm = mt*16 + gid;
                *(float2*)&Pw[lm*ZP + col]     = make_float2(p0, p1);
                *(float2*)&Pw[(lm+8)*ZP + col] = make_float2(p2, p3);
            }
        __syncwarp();
        #pragma unroll
        for (int ks = 0; ks < 8; ks++) {
            int k0 = ks * 8;
            unsigned int a[2][4];
            #pragma unroll
            for (int mt = 0; mt < 2; mt++) {
                int lm = mt*16 + gid;
                a[mt][0] = __float_as_uint(Pw[lm*ZP + k0 + tig]);
                a[mt][1] = __float_as_uint(Pw[(lm+8)*ZP + k0 + tig]);
                a[mt][2] = __float_as_uint(Pw[lm*ZP + k0 + tig + 4]);
                a[mt][3] = __float_as_uint(Pw[(lm+8)*ZP + k0 + tig + 4]);
            }
            #pragma unroll
            for (int nt = 0; nt < 4; nt++) {
                int nc = nt*8 + gid;
                unsigned int b0 = __float_as_uint(Vs[(jc*64 + k0 + tig)*VP + nc]);
                unsigned int b1 = __float_as_uint(Vs[(jc*64 + k0 + tig + 4)*VP + nc]);
                #pragma unroll
                for (int mt = 0; mt < 2; mt++)
                    MMA_TF32(o_acc[mt][nt], a[mt][0], a[mt][1], a[mt][2], a[mt][3], b0, b1);
            }
        }
        __syncwarp();
    }

    float inv[2][2];
    #pragma unroll
    for (int mt = 0; mt < 2; mt++)
        #pragma unroll
        for (int hf = 0; hf < 2; hf++) {
            float l = lsum[mt][hf];
            l += __shfl_xor_sync(0xffffffffu, l, 1);
            l += __shfl_xor_sync(0xffffffffu, l, 2);
            inv[mt][hf] = 1.f / l;
        }
    #pragma unroll
    for (int mt = 0; mt < 2; mt++)
        #pragma unroll
        for (int nt = 0; nt < 4; nt++) {
            int col = nt*8 + tig*2;
            #pragma unroll
            for (int hf = 0; hf < 2; hf++) {
                int row = m0 + mt*16 + gid + hf*8;
                float v0 = o_acc[mt][nt][hf*2]   * inv[mt][hf];
                float v1 = o_acc[mt][nt][hf*2+1] * inv[mt][hf];
                *(__half2*)(out + ((size_t)s*TLEN + row)*FDIM + hh*HDIM + col) =
                    __floats2half2_rn(v0, v1);
            }
        }
}

// ---------------------------------------------------------------------------
// Pack
// ---------------------------------------------------------------------------
__global__ void k_pack(const float* __restrict__ h, float* __restrict__ flat) {
    int idx = blockIdx.x * 256 + threadIdx.x;
    int n = idx >> 18;
    int d = idx & (DFLAT - 1);
    int c = d & 3;
    int f = (d >> 2) & 255;
    int t = d >> 10;
    flat[idx] = h[((size_t)(c*16 + n)*256 + t)*256 + f];
}

// ---------------------------------------------------------------------------
// Head stage 1 via tf32 mma with 3-term fp32-emulation split.
// ---------------------------------------------------------------------------
#define HM_AP 36
#define HM_ASZ (256*HM_AP)
#define HM_BSZ (16*HM_AP)
#define HM_SMEM ((2*(HM_ASZ + HM_BSZ))*4)

__global__ __launch_bounds__(256, 1) void k_head1_mma(
    const float* __restrict__ eW1, const float* __restrict__ aW1,
    const float* __restrict__ flat, float* __restrict__ z1p)
{
    int kc = blockIdx.x;
    int jb = blockIdx.y;
    const float* W = jb ? aW1 : eW1;
    extern __shared__ float smh[];
    float* Asm = smh;
    float* Bsm = smh + 2*HM_ASZ;
    int tid = threadIdx.x;
    int lane = tid & 31;
    int wid  = tid >> 5;
    int gid  = lane >> 2, tig = lane & 3;
    int m0 = wid * 32;
    size_t kbase = (size_t)kc * 4096;

    auto issue = [&](int st, int kb) {
        float* as = Asm + st*HM_ASZ;
        const float* Wb = W + kbase + kb*32;
        #pragma unroll
        for (int i = 0; i < 8; i++) {
            int idx = i*256 + tid;
            int r = idx >> 3, kq = (idx & 7) << 2;
            cpasync16(as + r*HM_AP + kq, Wb + (size_t)r*DFLAT + kq);
        }
        if (tid < 128) {
            float* bs = Bsm + st*HM_BSZ;
            int r = tid >> 3, kq = (tid & 7) << 2;
            cpasync16(bs + r*HM_AP + kq, flat + (size_t)r*DFLAT + kbase + kb*32 + kq);
        }
        asm volatile("cp.async.commit_group;\n");
    };

    float c[2][2][4];
    #pragma unroll
    for (int mt = 0; mt < 2; mt++)
        #pragma unroll
        for (int nt = 0; nt < 2; nt++)
            #pragma unroll
            for (int i = 0; i < 4; i++) c[mt][nt][i] = 0.f;

    issue(0, 0);
    for (int kb = 0; kb < 128; kb++) {
        int st = kb & 1;
        if (kb + 1 < 128) {
            issue(st ^ 1, kb + 1);
            asm volatile("cp.async.wait_group 1;\n");
        } else {
            asm volatile("cp.async.wait_group 0;\n");
        }
        __syncthreads();

        const float* as = Asm + st*HM_ASZ;
        const float* bs = Bsm + st*HM_BSZ;
        #pragma unroll
        for (int ks = 0; ks < 4; ks++) {
            int k0 = ks * 8;
            float af[2][4];
            unsigned int ahi[2][4], alo[2][4];
            #pragma unroll
            for (int mt = 0; mt < 2; mt++) {
                int mr = m0 + mt*16 + gid;
                af[mt][0] = as[mr*HM_AP + k0 + tig];
                af[mt][1] = as[(mr+8)*HM_AP + k0 + tig];
                af[mt][2] = as[mr*HM_AP + k0 + tig + 4];
                af[mt][3] = as[(mr+8)*HM_AP + k0 + tig + 4];
                #pragma unroll
                for (int i = 0; i < 4; i++) {
                    ahi[mt][i] = tf32_hi(af[mt][i]);
                    alo[mt][i] = __float_as_uint(af[mt][i] - __uint_as_float(ahi[mt][i]));
                }
            }
            #pragma unroll
            for (int nt = 0; nt < 2; nt++) {
                int nc = nt*8 + gid;
                float bf0 = bs[nc*HM_AP + k0 + tig];
                float bf1 = bs[nc*HM_AP + k0 + tig + 4];
                unsigned int bhi0 = tf32_hi(bf0), bhi1 = tf32_hi(bf1);
                unsigned int blo0 = __float_as_uint(bf0 - __uint_as_float(bhi0));
                unsigned int blo1 = __float_as_uint(bf1 - __uint_as_float(bhi1));
                #pragma unroll
                for (int mt = 0; mt < 2; mt++) {
                    MMA_TF32(c[mt][nt], ahi[mt][0], ahi[mt][1], ahi[mt][2], ahi[mt][3], bhi0, bhi1);
                    MMA_TF32(c[mt][nt], ahi[mt][0], ahi[mt][1], ahi[mt][2], ahi[mt][3], blo0, blo1);
                    MMA_TF32(c[mt][nt], alo[mt][0], alo[mt][1], alo[mt][2], alo[mt][3], bhi0, bhi1);
                }
            }
        }
        __syncthreads();
    }

    #pragma unroll
    for (int mt = 0; mt < 2; mt++)
        #pragma unroll
        for (int nt = 0; nt < 2; nt++) {
            int col = nt*8 + tig*2;
            #pragma unroll
            for (int hf = 0; hf < 2; hf++) {
                int row = m0 + mt*16 + gid + hf*8;
                int j = jb*256 + row;
                z1p[((size_t)j*16 + col    )*64 + kc] = c[mt][nt][hf*2];
                z1p[((size_t)j*16 + col + 1)*64 + kc] = c[mt][nt][hf*2 + 1];
            }
        }
}

__global__ void k_hred(const float* __restrict__ z1p, float* __restrict__ z1) {
    int idx = blockIdx.x * 256 + threadIdx.x;
    float s = 0.f;
    const float* p = z1p + (size_t)idx * 64;
    #pragma unroll 8
    for (int i = 0; i < 64; i++) s += p[i];
    z1[idx] = s;
}

// ---------------------------------------------------------------------------
// Head stage 2
// ---------------------------------------------------------------------------
__global__ __launch_bounds__(256) void k_head2(
    const float* __restrict__ z1,
    const float* __restrict__ eb1, const float* __restrict__ eg,
    const float* __restrict__ ebt, const float* __restrict__ eW2,
    const float* __restrict__ eb2, const float* __restrict__ eW3,
    const float* __restrict__ eb3, const float* __restrict__ eW4,
    const float* __restrict__ ab1, const float* __restrict__ ag,
    const float* __restrict__ abt, const float* __restrict__ aW2,
    const float* __restrict__ ab2, const float* __restrict__ aW3,
    const float* __restrict__ ab3, const float* __restrict__ aW4,
    float* __restrict__ out)
{
    int head = blockIdx.x;
    const float* b1 = head ? ab1 : eb1;
    const float* gg = head ? ag  : eg;
    const float* bt = head ? abt : ebt;
    const float* W2 = head ? aW2 : eW2;
    const float* b2 = head ? ab2 : eb2;
    const float* W3 = head ? aW3 : eW3;
    const float* b3 = head ? ab3 : eb3;
    const float* W4 = head ? aW4 : eW4;

    __shared__ float zs[256*17];
    int j = threadIdx.x;
    const float ibn = rsqrtf(1.f + 1e-5f);

    #pragma unroll
    for (int n = 0; n < 16; n++) {
        float v = z1[(size_t)(head*256 + j)*16 + n];
        v = (v + b1[j]) * ibn * gg[j] + bt[j];
        zs[j*17 + n] = fmaxf(v, 0.f);
    }
    __syncthreads();

    float acc[16];
    #pragma unroll
    for (int n = 0; n < 16; n++) acc[n] = b2[j];
    for (int k = 0; k < 256; k++) {
        float w = W2[j*256 + k];
        #pragma unroll
        for (int n = 0; n < 16; n++) acc[n] += w * zs[k*17 + n];
    }
    __syncthreads();
    #pragma unroll
    for (int n = 0; n < 16; n++) zs[j*17 + n] = fmaxf(acc[n], 0.f);
    __syncthreads();

    #pragma unroll
    for (int n = 0; n < 16; n++) acc[n] = b3[j];
    for (int k = 0; k < 256; k++) {
        float w = W3[j*256 + k];
        #pragma unroll
        for (int n = 0; n < 16; n++) acc[n] += w * zs[k*17 + n];
    }
    __syncthreads();
    #pragma unroll
    for (int n = 0; n < 16; n++) zs[j*17 + n] = fmaxf(acc[n], 0.f);
    __syncthreads();

    if (j < 32) {
        int i = j & 1, n = j >> 1;
        float a4 = 0.f;
        for (int k = 0; k < 256; k++) a4 += W4[i*256 + k] * zs[k*17 + n];
        float lo = head ? 0.f          : -0.78539818525f;
        float hi = head ? 6.28318548202f : 1.57079637050f;
        a4 = fminf(fmaxf(a4, lo), hi);
        out[n*4 + i*2 + head] = a4;
    }
}

// ---------------------------------------------------------------------------
// Host launcher
// ---------------------------------------------------------------------------
static void* symaddr_raw(const void* sym) {
    void* p = nullptr;
    cudaGetSymbolAddress(&p, sym);
    return p;
}

extern "C" void kernel_launch(void* const* d_in, const int* in_sizes, int n_in,
                              void* d_out, int out_size)
{
    const float* x    = (const float*)d_in[0];
    const float* Wq   = (const float*)d_in[1];
    const float* Wk   = (const float*)d_in[2];
    const float* Wv   = (const float*)d_in[3];
    const float* Wo   = (const float*)d_in[4];
    const float* bo   = (const float*)d_in[5];
    const float* ln1g = (const float*)d_in[6];
    const float* ln1b = (const float*)d_in[7];
    const float* ln2g = (const float*)d_in[8];
    const float* ln2b = (const float*)d_in[9];
    const float* ffW1 = (const float*)d_in[10];
    const float* ffb1 = (const float*)d_in[11];
    const float* ffW2 = (const float*)d_in[12];
    const float* ffb2 = (const float*)d_in[13];
    const float* eW1  = (const float*)d_in[14];
    const float* eb1  = (const float*)d_in[15];
    const float* eg   = (const float*)d_in[16];
    const float* ebt  = (const float*)d_in[17];
    const float* eW2  = (const float*)d_in[18];
    const float* eb2  = (const float*)d_in[19];
    const float* eW3  = (const float*)d_in[20];
    const float* eb3  = (const float*)d_in[21];
    const float* eW4  = (const float*)d_in[22];
    const float* aW1  = (const float*)d_in[23];
    const float* ab1  = (const float*)d_in[24];
    const float* ag   = (const float*)d_in[25];
    const float* abt  = (const float*)d_in[26];
    const float* aW2  = (const float*)d_in[27];
    const float* ab2  = (const float*)d_in[28];
    const float* aW3  = (const float*)d_in[29];
    const float* ab3  = (const float*)d_in[30];
    const float* aW4  = (const float*)d_in[31];
    float* out = (float*)d_out;

    float* ph    = (float*)symaddr_raw(g_h);
    float* px1   = (float*)symaddr_raw(g_x1);
    float* pflat = (float*)symaddr_raw(g_flat);
    float* pz1p  = (float*)symaddr_raw(g_z1p);
    float* pz1   = (float*)symaddr_raw(g_z1);
    __half* pattnh = (__half*)symaddr_raw(g_attnh);
    __half* px1h   = (__half*)symaddr_raw(g_x1h);
    __half* pffh   = (__half*)symaddr_raw(g_ffh);
    __half* pWoh   = (__half*)symaddr_raw(g_Woh);
    __half* pW1h   = (__half*)symaddr_raw(g_W1h);
    __half* pW2h   = (__half*)symaddr_raw(g_W2h);

    cudaFuncSetAttribute(k_attn_tc,   cudaFuncAttributeMaxDynamicSharedMemorySize, ATTN_SMEM);
    cudaFuncSetAttribute(k_gemm_f16,  cudaFuncAttributeMaxDynamicSharedMemorySize, F1_SMEM);
    cudaFuncSetAttribute(k_gemm_lnf,  cudaFuncAttributeMaxDynamicSharedMemorySize, GL_SMEM);
    cudaFuncSetAttribute(k_head1_mma, cudaFuncAttributeMaxDynamicSharedMemorySize, HM_SMEM);

    // weight conversion (deterministic, graph-capturable)
    k_cvt<<<(NLAYER*FDIM*FDIM + 255)/256, 256>>>(Wo,   pWoh, NLAYER*FDIM*FDIM);
    k_cvt<<<(NLAYER*EDIM*FDIM + 255)/256, 256>>>(ffW1, pW1h, NLAYER*EDIM*FDIM);
    k_cvt<<<(NLAYER*FDIM*EDIM + 255)/256, 256>>>(ffW2, pW2h, NLAYER*FDIM*EDIM);

    k_embed2<<<dim3(8, 8, 16), 256>>>(x, ph);

    for (int l = 0; l < NLAYER; l++) {
        k_attn_tc<<<dim3(SEQ, NHEAD), 256, ATTN_SMEM>>>(
            ph, Wq + l*1024, Wk + l*1024, Wv + l*1024, pattnh);
        // Wo proj + bias + resid(ph) + LN1 -> x1 (fp32) + x1h (fp16)
        k_gemm_lnf<<<MROWS/128, 256, GL_SMEM>>>(
            pattnh, pWoh + l*65536, bo + l*256, ph,
            ln1g + l*256, ln1b + l*256, px1, px1h, FDIM);
        // FFN1 + relu -> ffh (fp16)
        k_gemm_f16<<<dim3(MROWS/256, EDIM/128), 256, F1_SMEM>>>(
            px1h, pW1h + l*(EDIM*FDIM), ffb1 + l*EDIM, pffh, EDIM, FDIM);
        // FFN2 + bias + resid(x1) + LN2 -> h (fp32)
        k_gemm_lnf<<<MROWS/128, 256, GL_SMEM>>>(
            pffh, pW2h + l*(FDIM*EDIM), ffb2 + l*256, px1,
            ln2g + l*256, ln2b + l*256, ph, nullptr, EDIM);
    }

    k_pack<<<16384, 256>>>(ph, pflat);
    k_head1_mma<<<dim3(64, 2), 256, HM_SMEM>>>(eW1, aW1, pflat, pz1p);
    k_hred<<<32, 256>>>(pz1p, pz1);
    k_head2<<<2, 256>>>(pz1,
                        eb1, eg, ebt, eW2, eb2, eW3, eb3, eW4,
                        ab1, ag, abt, aW2, ab2, aW3, ab3, aW4,
                        out);
}

// round 13
// speedup vs baseline: 1.1654x; 1.1654x over previous
#include <cuda_runtime.h>
#include <cuda_bf16.h>
#include <math.h>
#include <stdint.h>

// ---------------------------------------------------------------------------
// Model dims
// ---------------------------------------------------------------------------
#define SEQ    64
#define TLEN   256
#define FDIM   256
#define NHEAD  8
#define HDIM   32
#define MROWS  16384
#define EDIM   1024
#define DFLAT  262144
#define NB     16
#define NLAYER 6

// ---------------------------------------------------------------------------
// Scratch
// ---------------------------------------------------------------------------
__device__ float g_h   [SEQ*TLEN*FDIM];
__device__ float g_attn[SEQ*TLEN*FDIM];
__device__ float g_x1  [SEQ*TLEN*FDIM];
__device__ float g_ff  [MROWS*EDIM];
__device__ float g_flat[NB*DFLAT];
__device__ float g_z1p [2*256*NB*64];
__device__ float g_z1  [2*256*NB];

// ---------------------------------------------------------------------------
// Embed (smem transpose, coalesced both sides)
// ---------------------------------------------------------------------------
__global__ __launch_bounds__(256) void k_embed2(
    const float* __restrict__ x, float* __restrict__ h)
{
    __shared__ float sm[4][32][33];
    int f0 = blockIdx.x * 32;
    int t0 = blockIdx.y * 32;
    int n  = blockIdx.z;
    int tid = threadIdx.x;
    int ti = tid & 31;
    int w8 = tid >> 5;

    #pragma unroll
    for (int i = 0; i < 4; i++) {
        int fi = w8 * 4 + i;
        float4 v = *(const float4*)(x + ((((size_t)n*256 + f0 + fi)*256 + t0 + ti) << 2));
        sm[0][ti][fi] = v.x;
        sm[1][ti][fi] = v.y;
        sm[2][ti][fi] = v.z;
        sm[3][ti][fi] = v.w;
    }
    __syncthreads();

    int fi = tid & 31;
    #pragma unroll
    for (int c = 0; c < 4; c++) {
        #pragma unroll
        for (int tt = 0; tt < 4; tt++) {
            int tiw = w8 * 4 + tt;
            int t = t0 + tiw;
            h[((size_t)(c*16 + n)*256 + t)*256 + f0 + fi] =
                sm[c][tiw][fi] + (float)t * (1.0f/255.0f);
        }
    }
}

// ---------------------------------------------------------------------------
// MMA helper (tf32 m16n8k8, fp32 accum)
// ---------------------------------------------------------------------------
#define MMA_TF32(C, A0, A1, A2, A3, B0, B1) \
    asm volatile( \
        "mma.sync.aligned.m16n8k8.row.col.f32.tf32.tf32.f32 " \
        "{%0,%1,%2,%3}, {%4,%5,%6,%7}, {%8,%9}, {%0,%1,%2,%3};\n" \
        : "+f"((C)[0]), "+f"((C)[1]), "+f"((C)[2]), "+f"((C)[3]) \
        : "r"(A0), "r"(A1), "r"(A2), "r"(A3), "r"(B0), "r"(B1))

__device__ __forceinline__ void cpasync16(void* sdst, const void* gsrc) {
    unsigned int s = (unsigned int)__cvta_generic_to_shared(sdst);
    asm volatile("cp.async.cg.shared.global [%0], [%1], 16;\n" :: "r"(s), "l"(gsrc));
}
__device__ __forceinline__ unsigned int tf32_hi(float a) {
    unsigned int h;
    asm("cvt.rna.tf32.f32 %0, %1;" : "=r"(h) : "f"(a));
    return h;
}

// ---------------------------------------------------------------------------
// tf32 GEMM (plain, relu): CTA tile 256x128, 8 warps of 64x64, 3-stage.
// ---------------------------------------------------------------------------
#define G2_ASZ (256*20)
#define G2_BSZ (128*20)
#define G2_SMEM ((3*(G2_ASZ + G2_BSZ))*4)

__global__ __launch_bounds__(256, 1) void k_gemm_tc2(
    const float* __restrict__ A, const float* __restrict__ B,
    const float* __restrict__ bias, float* __restrict__ out,
    int N, int K)
{
    extern __shared__ float smem2[];
    float* Asm = smem2;
    float* Bsm = smem2 + 3*G2_ASZ;
    int bm = blockIdx.x * 256, bn = blockIdx.y * 128;
    int tid = threadIdx.x;
    int lane = tid & 31;
    int wid  = tid >> 5;
    int gid  = lane >> 2, tig = lane & 3;
    int wm = (wid >> 1) * 64;
    int wn = (wid & 1) * 64;

    float c[4][8][4];
    #pragma unroll
    for (int mt = 0; mt < 4; mt++)
        #pragma unroll
        for (int nt = 0; nt < 8; nt++)
            #pragma unroll
            for (int i = 0; i < 4; i++) c[mt][nt][i] = 0.f;

    int KT = K >> 4;

    auto issue = [&](int st, int kb) {
        const float* Ab = A + (size_t)bm*K + kb*16;
        float* as = Asm + st*G2_ASZ;
        #pragma unroll
        for (int i = 0; i < 4; i++) {
            int idx = tid + i*256;
            int r = idx >> 2, kq = (idx & 3) << 2;
            cpasync16(as + r*20 + kq, Ab + (size_t)r*K + kq);
        }
        const float* Bb = B + (size_t)bn*K + kb*16;
        float* bs = Bsm + st*G2_BSZ;
        #pragma unroll
        for (int i = 0; i < 2; i++) {
            int idx = tid + i*256;
            int r = idx >> 2, kq = (idx & 3) << 2;
            cpasync16(bs + r*20 + kq, Bb + (size_t)r*K + kq);
        }
        asm volatile("cp.async.commit_group;\n");
    };

    issue(0, 0);
    issue(1, 1);
    int issued = 2;
    int st = 0, stn = 2;

    for (int kb = 0; kb < KT; kb++) {
        if (issued - kb - 1 >= 1) asm volatile("cp.async.wait_group 1;\n");
        else                      asm volatile("cp.async.wait_group 0;\n");
        __syncthreads();

        const float* as = Asm + st*G2_ASZ;
        const float* bs = Bsm + st*G2_BSZ;
        #pragma unroll
        for (int ks = 0; ks < 2; ks++) {
            int k0 = ks * 8;
            unsigned int a[4][4];
            #pragma unroll
            for (int mt = 0; mt < 4; mt++) {
                int mr = wm + mt*16 + gid;
                a[mt][0] = __float_as_uint(as[mr*20 + k0 + tig]);
                a[mt][1] = __float_as_uint(as[(mr+8)*20 + k0 + tig]);
                a[mt][2] = __float_as_uint(as[mr*20 + k0 + tig + 4]);
                a[mt][3] = __float_as_uint(as[(mr+8)*20 + k0 + tig + 4]);
            }
            unsigned int b[8][2];
            #pragma unroll
            for (int nt = 0; nt < 8; nt++) {
                int nc = wn + nt*8 + gid;
                b[nt][0] = __float_as_uint(bs[nc*20 + k0 + tig]);
                b[nt][1] = __float_as_uint(bs[nc*20 + k0 + tig + 4]);
            }
            #pragma unroll
            for (int mt = 0; mt < 4; mt++)
                #pragma unroll
                for (int nt = 0; nt < 8; nt++)
                    MMA_TF32(c[mt][nt], a[mt][0], a[mt][1], a[mt][2], a[mt][3],
                             b[nt][0], b[nt][1]);
        }

        if (kb + 2 < KT) { issue(stn, kb + 2); issued++; }
        st  = (st  == 2) ? 0 : st  + 1;
        stn = (stn == 2) ? 0 : stn + 1;
    }

    #pragma unroll
    for (int mt = 0; mt < 4; mt++) {
        #pragma unroll
        for (int nt = 0; nt < 8; nt++) {
            int col = bn + wn + nt*8 + (tig << 1);
            float bx = bias[col], by = bias[col + 1];
            #pragma unroll
            for (int hf = 0; hf < 2; hf++) {
                int row = bm + wm + mt*16 + gid + hf*8;
                float v0 = fmaxf(c[mt][nt][hf*2 + 0] + bx, 0.f);
                float v1 = fmaxf(c[mt][nt][hf*2 + 1] + by, 0.f);
                *(float2*)(out + (size_t)row*N + col) = make_float2(v0, v1);
            }
        }
    }
}

// ---------------------------------------------------------------------------
// tf32 GEMM + fused bias + residual + LayerNorm. N = 256 fixed.
// CTA tile 128x256, 8 warps of 32x128, 3-stage cp.async.
// ---------------------------------------------------------------------------
#define GL_ASZ (128*20)
#define GL_BSZ (256*20)
#define GL_SMEM ((3*(GL_ASZ + GL_BSZ))*4)

__global__ __launch_bounds__(256, 1) void k_gemm_ln(
    const float* __restrict__ A, const float* __restrict__ B,
    const float* __restrict__ bias, const float* __restrict__ resid,
    const float* __restrict__ lng, const float* __restrict__ lnb,
    float* __restrict__ out, int K)
{
    extern __shared__ float smem2[];
    float* Asm = smem2;
    float* Bsm = smem2 + 3*GL_ASZ;
    int bm = blockIdx.x * 128;
    int tid = threadIdx.x;
    int lane = tid & 31;
    int wid  = tid >> 5;
    int gid  = lane >> 2, tig = lane & 3;
    int wm = (wid >> 1) * 32;
    int wn = (wid & 1) * 128;

    float c[2][16][4];
    #pragma unroll
    for (int mt = 0; mt < 2; mt++)
        #pragma unroll
        for (int nt = 0; nt < 16; nt++)
            #pragma unroll
            for (int i = 0; i < 4; i++) c[mt][nt][i] = 0.f;

    int KT = K >> 4;

    auto issue = [&](int st, int kb) {
        const float* Ab = A + (size_t)bm*K + kb*16;
        float* as = Asm + st*GL_ASZ;
        #pragma unroll
        for (int i = 0; i < 2; i++) {
            int idx = tid + i*256;
            int r = idx >> 2, kq = (idx & 3) << 2;
            cpasync16(as + r*20 + kq, Ab + (size_t)r*K + kq);
        }
        const float* Bb = B + kb*16;
        float* bs = Bsm + st*GL_BSZ;
        #pragma unroll
        for (int i = 0; i < 4; i++) {
            int idx = tid + i*256;
            int r = idx >> 2, kq = (idx & 3) << 2;
            cpasync16(bs + r*20 + kq, Bb + (size_t)r*K + kq);
        }
        asm volatile("cp.async.commit_group;\n");
    };

    issue(0, 0);
    issue(1, 1);
    int issued = 2;
    int st = 0, stn = 2;

    for (int kb = 0; kb < KT; kb++) {
        if (issued - kb - 1 >= 1) asm volatile("cp.async.wait_group 1;\n");
        else                      asm volatile("cp.async.wait_group 0;\n");
        __syncthreads();

        const float* as = Asm + st*GL_ASZ;
        const float* bs = Bsm + st*GL_BSZ;
        #pragma unroll
        for (int ks = 0; ks < 2; ks++) {
            int k0 = ks * 8;
            unsigned int a[2][4];
            #pragma unroll
            for (int mt = 0; mt < 2; mt++) {
                int mr = wm + mt*16 + gid;
                a[mt][0] = __float_as_uint(as[mr*20 + k0 + tig]);
                a[mt][1] = __float_as_uint(as[(mr+8)*20 + k0 + tig]);
                a[mt][2] = __float_as_uint(as[mr*20 + k0 + tig + 4]);
                a[mt][3] = __float_as_uint(as[(mr+8)*20 + k0 + tig + 4]);
            }
            #pragma unroll
            for (int nt = 0; nt < 16; nt++) {
                int nc = wn + nt*8 + gid;
                unsigned int b0 = __float_as_uint(bs[nc*20 + k0 + tig]);
                unsigned int b1 = __float_as_uint(bs[nc*20 + k0 + tig + 4]);
                #pragma unroll
                for (int mt = 0; mt < 2; mt++)
                    MMA_TF32(c[mt][nt], a[mt][0], a[mt][1], a[mt][2], a[mt][3], b0, b1);
            }
        }

        if (kb + 2 < KT) { issue(stn, kb + 2); issued++; }
        st  = (st  == 2) ? 0 : st  + 1;
        stn = (stn == 2) ? 0 : stn + 1;
    }

    // ---- fused epilogue: bias + resid, then LayerNorm over 256 cols ----
    __syncthreads();
    float* red1 = smem2;
    float* red2 = smem2 + 256;

    #pragma unroll
    for (int mt = 0; mt < 2; mt++)
        #pragma unroll
        for (int nt = 0; nt < 16; nt++) {
            int col = wn + nt*8 + (tig << 1);
            float bx = bias[col], by = bias[col + 1];
            #pragma unroll
            for (int hf = 0; hf < 2; hf++) {
                int row = bm + wm + mt*16 + gid + hf*8;
                float2 r2 = *(const float2*)(resid + (size_t)row*256 + col);
                c[mt][nt][hf*2 + 0] += bx + r2.x;
                c[mt][nt][hf*2 + 1] += by + r2.y;
            }
        }

    #pragma unroll
    for (int mt = 0; mt < 2; mt++)
        #pragma unroll
        for (int hf = 0; hf < 2; hf++) {
            float s = 0.f;
            #pragma unroll
            for (int nt = 0; nt < 16; nt++)
                s += c[mt][nt][hf*2] + c[mt][nt][hf*2 + 1];
            s += __shfl_xor_sync(0xffffffffu, s, 1);
            s += __shfl_xor_sync(0xffffffffu, s, 2);
            if (tig == 0) {
                int r = wm + mt*16 + gid + hf*8;
                red1[(wid & 1)*128 + r] = s;
            }
        }
    __syncthreads();
    float mean[2][2];
    #pragma unroll
    for (int mt = 0; mt < 2; mt++)
        #pragma unroll
        for (int hf = 0; hf < 2; hf++) {
            int r = wm + mt*16 + gid + hf*8;
            mean[mt][hf] = (red1[r] + red1[128 + r]) * (1.f/256.f);
        }

    #pragma unroll
    for (int mt = 0; mt < 2; mt++)
        #pragma unroll
        for (int hf = 0; hf < 2; hf++) {
            float m = mean[mt][hf];
            float sq = 0.f;
            #pragma unroll
            for (int nt = 0; nt < 16; nt++) {
                float d0 = c[mt][nt][hf*2] - m;
                float d1 = c[mt][nt][hf*2 + 1] - m;
                sq += d0*d0 + d1*d1;
            }
            sq += __shfl_xor_sync(0xffffffffu, sq, 1);
            sq += __shfl_xor_sync(0xffffffffu, sq, 2);
            if (tig == 0) {
                int r = wm + mt*16 + gid + hf*8;
                red2[(wid & 1)*128 + r] = sq;
            }
        }
    __syncthreads();
    float rstd[2][2];
    #pragma unroll
    for (int mt = 0; mt < 2; mt++)
        #pragma unroll
        for (int hf = 0; hf < 2; hf++) {
            int r = wm + mt*16 + gid + hf*8;
            rstd[mt][hf] = rsqrtf((red2[r] + red2[128 + r]) * (1.f/256.f) + 1e-5f);
        }

    #pragma unroll
    for (int mt = 0; mt < 2; mt++)
        #pragma unroll
        for (int nt = 0; nt < 16; nt++) {
            int col = wn + nt*8 + (tig << 1);
            float2 gg = *(const float2*)(lng + col);
            float2 bb = *(const float2*)(lnb + col);
            #pragma unroll
            for (int hf = 0; hf < 2; hf++) {
                int row = bm + wm + mt*16 + gid + hf*8;
                float m = mean[mt][hf], rs = rstd[mt][hf];
                float v0 = (c[mt][nt][hf*2]     - m) * rs * gg.x + bb.x;
                float v1 = (c[mt][nt][hf*2 + 1] - m) * rs * gg.y + bb.y;
                *(float2*)(out + (size_t)row*256 + col) = make_float2(v0, v1);
            }
        }
}

// ---------------------------------------------------------------------------
// Tensor-core attention (legacy tf32 mma). One block per (seq, head).
// ---------------------------------------------------------------------------
#define ZP 36
#define VP 40
#define ATTN_SMEM ((3*256*ZP + 256*VP + 96*36) * 4)

__global__ __launch_bounds__(256, 1) void k_attn_tc(
    const float* __restrict__ h, const float* __restrict__ Wq,
    const float* __restrict__ Wk, const float* __restrict__ Wv,
    float* __restrict__ out)
{
    int s  = blockIdx.x;
    int hh = blockIdx.y;
    extern __shared__ float sma[];
    float* Z  = sma;
    float* Qs = sma + 256*ZP;
    float* Ks = sma + 2*256*ZP;
    float* Vs = sma + 3*256*ZP;
    float* Ws = sma + 3*256*ZP + 256*VP;

    int tid  = threadIdx.x;
    int lane = tid & 31;
    int wid  = tid >> 5;
    int gid  = lane >> 2, tig = lane & 3;
    int m0   = wid * 32;

    for (int i = tid; i < 1024; i += 256) {
        int r = i >> 5, c2 = i & 31;
        Ws[r*36 + c2]        = Wq[i];
        Ws[(32 + r)*36 + c2] = Wk[i];
        Ws[(64 + r)*36 + c2] = Wv[i];
    }
    {
        const float4* hrow = (const float4*)(h + ((size_t)s*TLEN + tid)*FDIM + hh*HDIM);
        #pragma unroll
        for (int i4 = 0; i4 < 8; i4++)
            *(float4*)&Z[tid*ZP + i4*4] = hrow[i4];
    }
    __syncthreads();

    {
        float aq[2][4][4], ak[2][4][4], av[2][4][4];
        #pragma unroll
        for (int mt = 0; mt < 2; mt++)
            #pragma unroll
            for (int nt = 0; nt < 4; nt++)
                #pragma unroll
                for (int i = 0; i < 4; i++) { aq[mt][nt][i]=0.f; ak[mt][nt][i]=0.f; av[mt][nt][i]=0.f; }

        #pragma unroll
        for (int ks = 0; ks < 4; ks++) {
            int k0 = ks * 8;
            unsigned int a[2][4];
            #pragma unroll
            for (int mt = 0; mt < 2; mt++) {
                int mr = m0 + mt*16 + gid;
                a[mt][0] = __float_as_uint(Z[mr*ZP + k0 + tig]);
                a[mt][1] = __float_as_uint(Z[(mr+8)*ZP + k0 + tig]);
                a[mt][2] = __float_as_uint(Z[mr*ZP + k0 + tig + 4]);
                a[mt][3] = __float_as_uint(Z[(mr+8)*ZP + k0 + tig + 4]);
            }
            #pragma unroll
            for (int nt = 0; nt < 4; nt++) {
                int nc = nt*8 + gid;
                unsigned int bq0 = __float_as_uint(Ws[nc*36 + k0 + tig]);
                unsigned int bq1 = __float_as_uint(Ws[nc*36 + k0 + tig + 4]);
                unsigned int bk0 = __float_as_uint(Ws[(32+nc)*36 + k0 + tig]);
                unsigned int bk1 = __float_as_uint(Ws[(32+nc)*36 + k0 + tig + 4]);
                unsigned int bv0 = __float_as_uint(Ws[(64+nc)*36 + k0 + tig]);
                unsigned int bv1 = __float_as_uint(Ws[(64+nc)*36 + k0 + tig + 4]);
                #pragma unroll
                for (int mt = 0; mt < 2; mt++) {
                    MMA_TF32(aq[mt][nt], a[mt][0], a[mt][1], a[mt][2], a[mt][3], bq0, bq1);
                    MMA_TF32(ak[mt][nt], a[mt][0], a[mt][1], a[mt][2], a[mt][3], bk0, bk1);
                    MMA_TF32(av[mt][nt], a[mt][0], a[mt][1], a[mt][2], a[mt][3], bv0, bv1);
                }
            }
        }
        #pragma unroll
        for (int mt = 0; mt < 2; mt++)
            #pragma unroll
            for (int nt = 0; nt < 4; nt++) {
                int col = nt*8 + tig*2;
                #pragma unroll
                for (int hf = 0; hf < 2; hf++) {
                    int rowq = m0 + mt*16 + gid + hf*8;
                    *(float2*)&Qs[rowq*ZP + col] = make_float2(aq[mt][nt][hf*2], aq[mt][nt][hf*2+1]);
                    *(float2*)&Ks[rowq*ZP + col] = make_float2(ak[mt][nt][hf*2], ak[mt][nt][hf*2+1]);
                    *(float2*)&Vs[rowq*VP + col] = make_float2(av[mt][nt][hf*2], av[mt][nt][hf*2+1]);
                }
            }
    }
    __syncthreads();

    float* Pw = Z + m0*ZP;
    float o_acc[2][4][4];
    float lsum[2][2];
    #pragma unroll
    for (int mt = 0; mt < 2; mt++) {
        lsum[mt][0] = 0.f; lsum[mt][1] = 0.f;
        #pragma unroll
        for (int nt = 0; nt < 4; nt++)
            #pragma unroll
            for (int i = 0; i < 4; i++) o_acc[mt][nt][i] = 0.f;
    }

    for (int jc = 0; jc < 4; jc++) {
        float s_acc[2][8][4];
        #pragma unroll
        for (int mt = 0; mt < 2; mt++)
            #pragma unroll
            for (int nt = 0; nt < 8; nt++)
                #pragma unroll
                for (int i = 0; i < 4; i++) s_acc[mt][nt][i] = 0.f;

        #pragma unroll
        for (int ks = 0; ks < 4; ks++) {
            int k0 = ks * 8;
            unsigned int a[2][4];
            #pragma unroll
            for (int mt = 0; mt < 2; mt++) {
                int mr = m0 + mt*16 + gid;
                a[mt][0] = __float_as_uint(Qs[mr*ZP + k0 + tig]);
                a[mt][1] = __float_as_uint(Qs[(mr+8)*ZP + k0 + tig]);
                a[mt][2] = __float_as_uint(Qs[mr*ZP + k0 + tig + 4]);
                a[mt][3] = __float_as_uint(Qs[(mr+8)*ZP + k0 + tig + 4]);
            }
            #pragma unroll
            for (int nt = 0; nt < 8; nt++) {
                int nc = jc*64 + nt*8 + gid;
                unsigned int b0 = __float_as_uint(Ks[nc*ZP + k0 + tig]);
                unsigned int b1 = __float_as_uint(Ks[nc*ZP + k0 + tig + 4]);
                #pragma unroll
                for (int mt = 0; mt < 2; mt++)
                    MMA_TF32(s_acc[mt][nt], a[mt][0], a[mt][1], a[mt][2], a[mt][3], b0, b1);
            }
        }
        #pragma unroll
        for (int mt = 0; mt < 2; mt++)
            #pragma unroll
            for (int nt = 0; nt < 8; nt++) {
                float p0 = __expf(s_acc[mt][nt][0] * 0.0625f);
                float p1 = __expf(s_acc[mt][nt][1] * 0.0625f);
                float p2 = __expf(s_acc[mt][nt][2] * 0.0625f);
                float p3 = __expf(s_acc[mt][nt][3] * 0.0625f);
                lsum[mt][0] += p0 + p1;
                lsum[mt][1] += p2 + p3;
                int col = nt*8 + tig*2;
                int lm = mt*16 + gid;
                *(float2*)&Pw[lm*ZP + col]     = make_float2(p0, p1);
                *(float2*)&Pw[(lm+8)*ZP + col] = make_float2(p2, p3);
            }
        __syncwarp();
        #pragma unroll
        for (int ks = 0; ks < 8; ks++) {
            int k0 = ks * 8;
            unsigned int a[2][4];
            #pragma unroll
            for (int mt = 0; mt < 2; mt++) {
                int lm = mt*16 + gid;
                a[mt][0] = __float_as_uint(Pw[lm*ZP + k0 + tig]);
                a[mt][1] = __float_as_uint(Pw[(lm+8)*ZP + k0 + tig]);
                a[mt][2] = __float_as_uint(Pw[lm*ZP + k0 + tig + 4]);
                a[mt][3] = __float_as_uint(Pw[(lm+8)*ZP + k0 + tig + 4]);
            }
            #pragma unroll
            for (int nt = 0; nt < 4; nt++) {
                int nc = nt*8 + gid;
                unsigned int b0 = __float_as_uint(Vs[(jc*64 + k0 + tig)*VP + nc]);
                unsigned int b1 = __float_as_uint(Vs[(jc*64 + k0 + tig + 4)*VP + nc]);
                #pragma unroll
                for (int mt = 0; mt < 2; mt++)
                    MMA_TF32(o_acc[mt][nt], a[mt][0], a[mt][1], a[mt][2], a[mt][3], b0, b1);
            }
        }
        __syncwarp();
    }

    float inv[2][2];
    #pragma unroll
    for (int mt = 0; mt < 2; mt++)
        #pragma unroll
        for (int hf = 0; hf < 2; hf++) {
            float l = lsum[mt][hf];
            l += __shfl_xor_sync(0xffffffffu, l, 1);
            l += __shfl_xor_sync(0xffffffffu, l, 2);
            inv[mt][hf] = 1.f / l;
        }
    #pragma unroll
    for (int mt = 0; mt < 2; mt++)
        #pragma unroll
        for (int nt = 0; nt < 4; nt++) {
            int col = nt*8 + tig*2;
            #pragma unroll
            for (int hf = 0; hf < 2; hf++) {
                int row = m0 + mt*16 + gid + hf*8;
                float v0 = o_acc[mt][nt][hf*2]   * inv[mt][hf];
                float v1 = o_acc[mt][nt][hf*2+1] * inv[mt][hf];
                *(float2*)(out + ((size_t)s*TLEN + row)*FDIM + hh*HDIM + col) = make_float2(v0, v1);
            }
        }
}

// ---------------------------------------------------------------------------
// Pack with smem transpose: coalesced read of 4 c-rows, coalesced write of
// the interleaved 1024-float run. Block = (t, n).
// flat[n][(t*256+f)*4 + c] = h[(c*16+n)][t][f]
// ---------------------------------------------------------------------------
__global__ __launch_bounds__(256) void k_pack2(
    const float* __restrict__ h, float* __restrict__ flat)
{
    __shared__ float sm[4][260];
    int t = blockIdx.x;
    int n = blockIdx.y;
    int tid = threadIdx.x;

    #pragma unroll
    for (int c = 0; c < 4; c++)
        sm[c][tid] = h[((size_t)(c*16 + n)*256 + t)*256 + tid];
    __syncthreads();

    float* dst = flat + (size_t)n*DFLAT + t*1024;
    #pragma unroll
    for (int j = 0; j < 4; j++) {
        int i = j*256 + tid;
        dst[i] = sm[i & 3][i >> 2];
    }
}

// ---------------------------------------------------------------------------
// Head stage 1 via tf32 mma with 3-term fp32-emulation split.
// ---------------------------------------------------------------------------
#define HM_AP 36
#define HM_ASZ (256*HM_AP)
#define HM_BSZ (16*HM_AP)
#define HM_SMEM ((2*(HM_ASZ + HM_BSZ))*4)

__global__ __launch_bounds__(256, 1) void k_head1_mma(
    const float* __restrict__ eW1, const float* __restrict__ aW1,
    const float* __restrict__ flat, float* __restrict__ z1p)
{
    int kc = blockIdx.x;
    int jb = blockIdx.y;
    const float* W = jb ? aW1 : eW1;
    extern __shared__ float smh[];
    float* Asm = smh;
    float* Bsm = smh + 2*HM_ASZ;
    int tid = threadIdx.x;
    int lane = tid & 31;
    int wid  = tid >> 5;
    int gid  = lane >> 2, tig = lane & 3;
    int m0 = wid * 32;
    size_t kbase = (size_t)kc * 4096;

    auto issue = [&](int st, int kb) {
        float* as = Asm + st*HM_ASZ;
        const float* Wb = W + kbase + kb*32;
        #pragma unroll
        for (int i = 0; i < 8; i++) {
            int idx = i*256 + tid;
            int r = idx >> 3, kq = (idx & 7) << 2;
            cpasync16(as + r*HM_AP + kq, Wb + (size_t)r*DFLAT + kq);
        }
        if (tid < 128) {
            float* bs = Bsm + st*HM_BSZ;
            int r = tid >> 3, kq = (tid & 7) << 2;
            cpasync16(bs + r*HM_AP + kq, flat + (size_t)r*DFLAT + kbase + kb*32 + kq);
        }
        asm volatile("cp.async.commit_group;\n");
    };

    float c[2][2][4];
    #pragma unroll
    for (int mt = 0; mt < 2; mt++)
        #pragma unroll
        for (int nt = 0; nt < 2; nt++)
            #pragma unroll
            for (int i = 0; i < 4; i++) c[mt][nt][i] = 0.f;

    issue(0, 0);
    for (int kb = 0; kb < 128; kb++) {
        int st = kb & 1;
        if (kb + 1 < 128) {
            issue(st ^ 1, kb + 1);
            asm volatile("cp.async.wait_group 1;\n");
        } else {
            asm volatile("cp.async.wait_group 0;\n");
        }
        __syncthreads();

        const float* as = Asm + st*HM_ASZ;
        const float* bs = Bsm + st*HM_BSZ;
        #pragma unroll
        for (int ks = 0; ks < 4; ks++) {
            int k0 = ks * 8;
            float af[2][4];
            unsigned int ahi[2][4], alo[2][4];
            #pragma unroll
            for (int mt = 0; mt < 2; mt++) {
                int mr = m0 + mt*16 + gid;
                af[mt][0] = as[mr*HM_AP + k0 + tig];
                af[mt][1] = as[(mr+8)*HM_AP + k0 + tig];
                af[mt][2] = as[mr*HM_AP + k0 + tig + 4];
                af[mt][3] = as[(mr+8)*HM_AP + k0 + tig + 4];
                #pragma unroll
                for (int i = 0; i < 4; i++) {
                    ahi[mt][i] = tf32_hi(af[mt][i]);
                    alo[mt][i] = __float_as_uint(af[mt][i] - __uint_as_float(ahi[mt][i]));
                }
            }
            #pragma unroll
            for (int nt = 0; nt < 2; nt++) {
                int nc = nt*8 + gid;
                float bf0 = bs[nc*HM_AP + k0 + tig];
                float bf1 = bs[nc*HM_AP + k0 + tig + 4];
                unsigned int bhi0 = tf32_hi(bf0), bhi1 = tf32_hi(bf1);
                unsigned int blo0 = __float_as_uint(bf0 - __uint_as_float(bhi0));
                unsigned int blo1 = __float_as_uint(bf1 - __uint_as_float(bhi1));
                #pragma unroll
                for (int mt = 0; mt < 2; mt++) {
                    MMA_TF32(c[mt][nt], ahi[mt][0], ahi[mt][1], ahi[mt][2], ahi[mt][3], bhi0, bhi1);
                    MMA_TF32(c[mt][nt], ahi[mt][0], ahi[mt][1], ahi[mt][2], ahi[mt][3], blo0, blo1);
                    MMA_TF32(c[mt][nt], alo[mt][0], alo[mt][1], alo[mt][2], alo[mt][3], bhi0, bhi1);
                }
            }
        }
        __syncthreads();
    }

    #pragma unroll
    for (int mt = 0; mt < 2; mt++)
        #pragma unroll
        for (int nt = 0; nt < 2; nt++) {
            int col = nt*8 + tig*2;
            #pragma unroll
            for (int hf = 0; hf < 2; hf++) {
                int row = m0 + mt*16 + gid + hf*8;
                int j = jb*256 + row;
                z1p[((size_t)j*16 + col    )*64 + kc] = c[mt][nt][hf*2];
                z1p[((size_t)j*16 + col + 1)*64 + kc] = c[mt][nt][hf*2 + 1];
            }
        }
}

__global__ void k_hred(const float* __restrict__ z1p, float* __restrict__ z1) {
    int idx = blockIdx.x * 256 + threadIdx.x;
    float s = 0.f;
    const float* p = z1p + (size_t)idx * 64;
    #pragma unroll 8
    for (int i = 0; i < 64; i++) s += p[i];
    z1[idx] = s;
}

// ---------------------------------------------------------------------------
// Head stage 2
// ---------------------------------------------------------------------------
__global__ __launch_bounds__(256) void k_head2(
    const float* __restrict__ z1,
    const float* __restrict__ eb1, const float* __restrict__ eg,
    const float* __restrict__ ebt, const float* __restrict__ eW2,
    const float* __restrict__ eb2, const float* __restrict__ eW3,
    const float* __restrict__ eb3, const float* __restrict__ eW4,
    const float* __restrict__ ab1, const float* __restrict__ ag,
    const float* __restrict__ abt, const float* __restrict__ aW2,
    const float* __restrict__ ab2, const float* __restrict__ aW3,
    const float* __restrict__ ab3, const float* __restrict__ aW4,
    float* __restrict__ out)
{
    int head = blockIdx.x;
    const float* b1 = head ? ab1 : eb1;
    const float* gg = head ? ag  : eg;
    const float* bt = head ? abt : ebt;
    const float* W2 = head ? aW2 : eW2;
    const float* b2 = head ? ab2 : eb2;
    const float* W3 = head ? aW3 : eW3;
    const float* b3 = head ? ab3 : eb3;
    const float* W4 = head ? aW4 : eW4;

    __shared__ float zs[256*17];
    int j = threadIdx.x;
    const float ibn = rsqrtf(1.f + 1e-5f);

    #pragma unroll
    for (int n = 0; n < 16; n++) {
        float v = z1[(size_t)(head*256 + j)*16 + n];
        v = (v + b1[j]) * ibn * gg[j] + bt[j];
        zs[j*17 + n] = fmaxf(v, 0.f);
    }
    __syncthreads();

    float acc[16];
    #pragma unroll
    for (int n = 0; n < 16; n++) acc[n] = b2[j];
    for (int k = 0; k < 256; k++) {
        float w = W2[j*256 + k];
        #pragma unroll
        for (int n = 0; n < 16; n++) acc[n] += w * zs[k*17 + n];
    }
    __syncthreads();
    #pragma unroll
    for (int n = 0; n < 16; n++) zs[j*17 + n] = fmaxf(acc[n], 0.f);
    __syncthreads();

    #pragma unroll
    for (int n = 0; n < 16; n++) acc[n] = b3[j];
    for (int k = 0; k < 256; k++) {
        float w = W3[j*256 + k];
        #pragma unroll
        for (int n = 0; n < 16; n++) acc[n] += w * zs[k*17 + n];
    }
    __syncthreads();
    #pragma unroll
    for (int n = 0; n < 16; n++) zs[j*17 + n] = fmaxf(acc[n], 0.f);
    __syncthreads();

    if (j < 32) {
        int i = j & 1, n = j >> 1;
        float a4 = 0.f;
        for (int k = 0; k < 256; k++) a4 += W4[i*256 + k] * zs[k*17 + n];
        float lo = head ? 0.f          : -0.78539818525f;
        float hi = head ? 6.28318548202f : 1.57079637050f;
        a4 = fminf(fmaxf(a4, lo), hi);
        out[n*4 + i*2 + head] = a4;
    }
}

// ---------------------------------------------------------------------------
// Host launcher
// ---------------------------------------------------------------------------
static float* symaddr(const void* sym) {
    void* p = nullptr;
    cudaGetSymbolAddress(&p, sym);
    return (float*)p;
}

extern "C" void kernel_launch(void* const* d_in, const int* in_sizes, int n_in,
                              void* d_out, int out_size)
{
    const float* x    = (const float*)d_in[0];
    const float* Wq   = (const float*)d_in[1];
    const float* Wk   = (const float*)d_in[2];
    const float* Wv   = (const float*)d_in[3];
    const float* Wo   = (const float*)d_in[4];
    const float* bo   = (const float*)d_in[5];
    const float* ln1g = (const float*)d_in[6];
    const float* ln1b = (const float*)d_in[7];
    const float* ln2g = (const float*)d_in[8];
    const float* ln2b = (const float*)d_in[9];
    const float* ffW1 = (const float*)d_in[10];
    const float* ffb1 = (const float*)d_in[11];
    const float* ffW2 = (const float*)d_in[12];
    const float* ffb2 = (const float*)d_in[13];
    const float* eW1  = (const float*)d_in[14];
    const float* eb1  = (const float*)d_in[15];
    const float* eg   = (const float*)d_in[16];
    const float* ebt  = (const float*)d_in[17];
    const float* eW2  = (const float*)d_in[18];
    const float* eb2  = (const float*)d_in[19];
    const float* eW3  = (const float*)d_in[20];
    const float* eb3  = (const float*)d_in[21];
    const float* eW4  = (const float*)d_in[22];
    const float* aW1  = (const float*)d_in[23];
    const float* ab1  = (const float*)d_in[24];
    const float* ag   = (const float*)d_in[25];
    const float* abt  = (const float*)d_in[26];
    const float* aW2  = (const float*)d_in[27];
    const float* ab2  = (const float*)d_in[28];
    const float* aW3  = (const float*)d_in[29];
    const float* ab3  = (const float*)d_in[30];
    const float* aW4  = (const float*)d_in[31];
    float* out = (float*)d_out;

    float* ph    = symaddr(g_h);
    float* pattn = symaddr(g_attn);
    float* px1   = symaddr(g_x1);
    float* pff   = symaddr(g_ff);
    float* pflat = symaddr(g_flat);
    float* pz1p  = symaddr(g_z1p);
    float* pz1   = symaddr(g_z1);

    cudaFuncSetAttribute(k_attn_tc,   cudaFuncAttributeMaxDynamicSharedMemorySize, ATTN_SMEM);
    cudaFuncSetAttribute(k_gemm_tc2,  cudaFuncAttributeMaxDynamicSharedMemorySize, G2_SMEM);
    cudaFuncSetAttribute(k_gemm_ln,   cudaFuncAttributeMaxDynamicSharedMemorySize, GL_SMEM);
    cudaFuncSetAttribute(k_head1_mma, cudaFuncAttributeMaxDynamicSharedMemorySize, HM_SMEM);

    k_embed2<<<dim3(8, 8, 16), 256>>>(x, ph);

    for (int l = 0; l < NLAYER; l++) {
        k_attn_tc<<<dim3(SEQ, NHEAD), 256, ATTN_SMEM>>>(
            ph, Wq + l*1024, Wk + l*1024, Wv + l*1024, pattn);
        k_gemm_ln<<<MROWS/128, 256, GL_SMEM>>>(
            pattn, Wo + l*65536, bo + l*256, ph,
            ln1g + l*256, ln1b + l*256, px1, FDIM);
        k_gemm_tc2<<<dim3(MROWS/256, EDIM/128), 256, G2_SMEM>>>(
            px1, ffW1 + l*(EDIM*FDIM), ffb1 + l*EDIM, pff, EDIM, FDIM);
        k_gemm_ln<<<MROWS/128, 256, GL_SMEM>>>(
            pff, ffW2 + l*(FDIM*EDIM), ffb2 + l*256, px1,
            ln2g + l*256, ln2b + l*256, ph, EDIM);
    }

    k_pack2<<<dim3(TLEN, NB), 256>>>(ph, pflat);
    k_head1_mma<<<dim3(64, 2), 256, HM_SMEM>>>(eW1, aW1, pflat, pz1p);
    k_hred<<<32, 256>>>(pz1p, pz1);
    k_head2<<<2, 256>>>(pz1,
                        eb1, eg, ebt, eW2, eb2, eW3, eb3, eW4,
                        ab1, ag, abt, aW2, ab2, aW3, ab3, aW4,
                        out);
}

// round 14
// speedup vs baseline: 1.1957x; 1.0260x over previous
#include <cuda_runtime.h>
#include <cuda_bf16.h>
#include <math.h>
#include <stdint.h>

// ---------------------------------------------------------------------------
// Model dims
// ---------------------------------------------------------------------------
#define SEQ    64
#define TLEN   256
#define FDIM   256
#define NHEAD  8
#define HDIM   32
#define MROWS  16384
#define EDIM   1024
#define DFLAT  262144
#define NB     16
#define NLAYER 6

// ---------------------------------------------------------------------------
// Scratch
// ---------------------------------------------------------------------------
__device__ float g_h   [SEQ*TLEN*FDIM];
__device__ float g_attn[SEQ*TLEN*FDIM];
__device__ float g_x1  [SEQ*TLEN*FDIM];
__device__ float g_ff  [MROWS*EDIM];
__device__ float g_flat[NB*DFLAT];
__device__ float g_z1p [2*256*NB*64];
__device__ float g_z1  [2*256*NB];

// ---------------------------------------------------------------------------
// Embed (smem transpose, coalesced both sides)
// ---------------------------------------------------------------------------
__global__ __launch_bounds__(256) void k_embed2(
    const float* __restrict__ x, float* __restrict__ h)
{
    __shared__ float sm[4][32][33];
    int f0 = blockIdx.x * 32;
    int t0 = blockIdx.y * 32;
    int n  = blockIdx.z;
    int tid = threadIdx.x;
    int ti = tid & 31;
    int w8 = tid >> 5;

    #pragma unroll
    for (int i = 0; i < 4; i++) {
        int fi = w8 * 4 + i;
        float4 v = *(const float4*)(x + ((((size_t)n*256 + f0 + fi)*256 + t0 + ti) << 2));
        sm[0][ti][fi] = v.x;
        sm[1][ti][fi] = v.y;
        sm[2][ti][fi] = v.z;
        sm[3][ti][fi] = v.w;
    }
    __syncthreads();

    int fi = tid & 31;
    #pragma unroll
    for (int c = 0; c < 4; c++) {
        #pragma unroll
        for (int tt = 0; tt < 4; tt++) {
            int tiw = w8 * 4 + tt;
            int t = t0 + tiw;
            h[((size_t)(c*16 + n)*256 + t)*256 + f0 + fi] =
                sm[c][tiw][fi] + (float)t * (1.0f/255.0f);
        }
    }
}

// ---------------------------------------------------------------------------
// MMA helper (tf32 m16n8k8, fp32 accum)
// ---------------------------------------------------------------------------
#define MMA_TF32(C, A0, A1, A2, A3, B0, B1) \
    asm volatile( \
        "mma.sync.aligned.m16n8k8.row.col.f32.tf32.tf32.f32 " \
        "{%0,%1,%2,%3}, {%4,%5,%6,%7}, {%8,%9}, {%0,%1,%2,%3};\n" \
        : "+f"((C)[0]), "+f"((C)[1]), "+f"((C)[2]), "+f"((C)[3]) \
        : "r"(A0), "r"(A1), "r"(A2), "r"(A3), "r"(B0), "r"(B1))

__device__ __forceinline__ void cpasync16(void* sdst, const void* gsrc) {
    unsigned int s = (unsigned int)__cvta_generic_to_shared(sdst);
    asm volatile("cp.async.cg.shared.global [%0], [%1], 16;\n" :: "r"(s), "l"(gsrc));
}
__device__ __forceinline__ unsigned int tf32_hi(float a) {
    unsigned int h;
    asm("cvt.rna.tf32.f32 %0, %1;" : "=r"(h) : "f"(a));
    return h;
}

// ---------------------------------------------------------------------------
// tf32 GEMM (plain, relu): CTA tile 256x128, 8 warps of 64x64, 3-stage.
// ---------------------------------------------------------------------------
#define G2_ASZ (256*20)
#define G2_BSZ (128*20)
#define G2_SMEM ((3*(G2_ASZ + G2_BSZ))*4)

__global__ __launch_bounds__(256, 1) void k_gemm_tc2(
    const float* __restrict__ A, const float* __restrict__ B,
    const float* __restrict__ bias, float* __restrict__ out,
    int N, int K)
{
    extern __shared__ float smem2[];
    float* Asm = smem2;
    float* Bsm = smem2 + 3*G2_ASZ;
    int bm = blockIdx.x * 256, bn = blockIdx.y * 128;
    int tid = threadIdx.x;
    int lane = tid & 31;
    int wid  = tid >> 5;
    int gid  = lane >> 2, tig = lane & 3;
    int wm = (wid >> 1) * 64;
    int wn = (wid & 1) * 64;

    float c[4][8][4];
    #pragma unroll
    for (int mt = 0; mt < 4; mt++)
        #pragma unroll
        for (int nt = 0; nt < 8; nt++)
            #pragma unroll
            for (int i = 0; i < 4; i++) c[mt][nt][i] = 0.f;

    int KT = K >> 4;

    auto issue = [&](int st, int kb) {
        const float* Ab = A + (size_t)bm*K + kb*16;
        float* as = Asm + st*G2_ASZ;
        #pragma unroll
        for (int i = 0; i < 4; i++) {
            int idx = tid + i*256;
            int r = idx >> 2, kq = (idx & 3) << 2;
            cpasync16(as + r*20 + kq, Ab + (size_t)r*K + kq);
        }
        const float* Bb = B + (size_t)bn*K + kb*16;
        float* bs = Bsm + st*G2_BSZ;
        #pragma unroll
        for (int i = 0; i < 2; i++) {
            int idx = tid + i*256;
            int r = idx >> 2, kq = (idx & 3) << 2;
            cpasync16(bs + r*20 + kq, Bb + (size_t)r*K + kq);
        }
        asm volatile("cp.async.commit_group;\n");
    };

    issue(0, 0);
    issue(1, 1);
    int issued = 2;
    int st = 0, stn = 2;

    for (int kb = 0; kb < KT; kb++) {
        if (issued - kb - 1 >= 1) asm volatile("cp.async.wait_group 1;\n");
        else                      asm volatile("cp.async.wait_group 0;\n");
        __syncthreads();

        const float* as = Asm + st*G2_ASZ;
        const float* bs = Bsm + st*G2_BSZ;
        #pragma unroll
        for (int ks = 0; ks < 2; ks++) {
            int k0 = ks * 8;
            unsigned int a[4][4];
            #pragma unroll
            for (int mt = 0; mt < 4; mt++) {
                int mr = wm + mt*16 + gid;
                a[mt][0] = __float_as_uint(as[mr*20 + k0 + tig]);
                a[mt][1] = __float_as_uint(as[(mr+8)*20 + k0 + tig]);
                a[mt][2] = __float_as_uint(as[mr*20 + k0 + tig + 4]);
                a[mt][3] = __float_as_uint(as[(mr+8)*20 + k0 + tig + 4]);
            }
            unsigned int b[8][2];
            #pragma unroll
            for (int nt = 0; nt < 8; nt++) {
                int nc = wn + nt*8 + gid;
                b[nt][0] = __float_as_uint(bs[nc*20 + k0 + tig]);
                b[nt][1] = __float_as_uint(bs[nc*20 + k0 + tig + 4]);
            }
            #pragma unroll
            for (int mt = 0; mt < 4; mt++)
                #pragma unroll
                for (int nt = 0; nt < 8; nt++)
                    MMA_TF32(c[mt][nt], a[mt][0], a[mt][1], a[mt][2], a[mt][3],
                             b[nt][0], b[nt][1]);
        }

        if (kb + 2 < KT) { issue(stn, kb + 2); issued++; }
        st  = (st  == 2) ? 0 : st  + 1;
        stn = (stn == 2) ? 0 : stn + 1;
    }

    #pragma unroll
    for (int mt = 0; mt < 4; mt++) {
        #pragma unroll
        for (int nt = 0; nt < 8; nt++) {
            int col = bn + wn + nt*8 + (tig << 1);
            float bx = bias[col], by = bias[col + 1];
            #pragma unroll
            for (int hf = 0; hf < 2; hf++) {
                int row = bm + wm + mt*16 + gid + hf*8;
                float v0 = fmaxf(c[mt][nt][hf*2 + 0] + bx, 0.f);
                float v1 = fmaxf(c[mt][nt][hf*2 + 1] + by, 0.f);
                *(float2*)(out + (size_t)row*N + col) = make_float2(v0, v1);
            }
        }
    }
}

// ---------------------------------------------------------------------------
// tf32 GEMM + fused bias + residual + LayerNorm. N = 256 fixed.
// ---------------------------------------------------------------------------
#define GL_ASZ (128*20)
#define GL_BSZ (256*20)
#define GL_SMEM ((3*(GL_ASZ + GL_BSZ))*4)

__global__ __launch_bounds__(256, 1) void k_gemm_ln(
    const float* __restrict__ A, const float* __restrict__ B,
    const float* __restrict__ bias, const float* __restrict__ resid,
    const float* __restrict__ lng, const float* __restrict__ lnb,
    float* __restrict__ out, int K)
{
    extern __shared__ float smem2[];
    float* Asm = smem2;
    float* Bsm = smem2 + 3*GL_ASZ;
    int bm = blockIdx.x * 128;
    int tid = threadIdx.x;
    int lane = tid & 31;
    int wid  = tid >> 5;
    int gid  = lane >> 2, tig = lane & 3;
    int wm = (wid >> 1) * 32;
    int wn = (wid & 1) * 128;

    float c[2][16][4];
    #pragma unroll
    for (int mt = 0; mt < 2; mt++)
        #pragma unroll
        for (int nt = 0; nt < 16; nt++)
            #pragma unroll
            for (int i = 0; i < 4; i++) c[mt][nt][i] = 0.f;

    int KT = K >> 4;

    auto issue = [&](int st, int kb) {
        const float* Ab = A + (size_t)bm*K + kb*16;
        float* as = Asm + st*GL_ASZ;
        #pragma unroll
        for (int i = 0; i < 2; i++) {
            int idx = tid + i*256;
            int r = idx >> 2, kq = (idx & 3) << 2;
            cpasync16(as + r*20 + kq, Ab + (size_t)r*K + kq);
        }
        const float* Bb = B + kb*16;
        float* bs = Bsm + st*GL_BSZ;
        #pragma unroll
        for (int i = 0; i < 4; i++) {
            int idx = tid + i*256;
            int r = idx >> 2, kq = (idx & 3) << 2;
            cpasync16(bs + r*20 + kq, Bb + (size_t)r*K + kq);
        }
        asm volatile("cp.async.commit_group;\n");
    };

    issue(0, 0);
    issue(1, 1);
    int issued = 2;
    int st = 0, stn = 2;

    for (int kb = 0; kb < KT; kb++) {
        if (issued - kb - 1 >= 1) asm volatile("cp.async.wait_group 1;\n");
        else                      asm volatile("cp.async.wait_group 0;\n");
        __syncthreads();

        const float* as = Asm + st*GL_ASZ;
        const float* bs = Bsm + st*GL_BSZ;
        #pragma unroll
        for (int ks = 0; ks < 2; ks++) {
            int k0 = ks * 8;
            unsigned int a[2][4];
            #pragma unroll
            for (int mt = 0; mt < 2; mt++) {
                int mr = wm + mt*16 + gid;
                a[mt][0] = __float_as_uint(as[mr*20 + k0 + tig]);
                a[mt][1] = __float_as_uint(as[(mr+8)*20 + k0 + tig]);
                a[mt][2] = __float_as_uint(as[mr*20 + k0 + tig + 4]);
                a[mt][3] = __float_as_uint(as[(mr+8)*20 + k0 + tig + 4]);
            }
            #pragma unroll
            for (int nt = 0; nt < 16; nt++) {
                int nc = wn + nt*8 + gid;
                unsigned int b0 = __float_as_uint(bs[nc*20 + k0 + tig]);
                unsigned int b1 = __float_as_uint(bs[nc*20 + k0 + tig + 4]);
                #pragma unroll
                for (int mt = 0; mt < 2; mt++)
                    MMA_TF32(c[mt][nt], a[mt][0], a[mt][1], a[mt][2], a[mt][3], b0, b1);
            }
        }

        if (kb + 2 < KT) { issue(stn, kb + 2); issued++; }
        st  = (st  == 2) ? 0 : st  + 1;
        stn = (stn == 2) ? 0 : stn + 1;
    }

    // ---- fused epilogue: bias + resid, then LayerNorm over 256 cols ----
    __syncthreads();
    float* red1 = smem2;
    float* red2 = smem2 + 256;

    #pragma unroll
    for (int mt = 0; mt < 2; mt++)
        #pragma unroll
        for (int nt = 0; nt < 16; nt++) {
            int col = wn + nt*8 + (tig << 1);
            float bx = bias[col], by = bias[col + 1];
            #pragma unroll
            for (int hf = 0; hf < 2; hf++) {
                int row = bm + wm + mt*16 + gid + hf*8;
                float2 r2 = *(const float2*)(resid + (size_t)row*256 + col);
                c[mt][nt][hf*2 + 0] += bx + r2.x;
                c[mt][nt][hf*2 + 1] += by + r2.y;
            }
        }

    #pragma unroll
    for (int mt = 0; mt < 2; mt++)
        #pragma unroll
        for (int hf = 0; hf < 2; hf++) {
            float s = 0.f;
            #pragma unroll
            for (int nt = 0; nt < 16; nt++)
                s += c[mt][nt][hf*2] + c[mt][nt][hf*2 + 1];
            s += __shfl_xor_sync(0xffffffffu, s, 1);
            s += __shfl_xor_sync(0xffffffffu, s, 2);
            if (tig == 0) {
                int r = wm + mt*16 + gid + hf*8;
                red1[(wid & 1)*128 + r] = s;
            }
        }
    __syncthreads();
    float mean[2][2];
    #pragma unroll
    for (int mt = 0; mt < 2; mt++)
        #pragma unroll
        for (int hf = 0; hf < 2; hf++) {
            int r = wm + mt*16 + gid + hf*8;
            mean[mt][hf] = (red1[r] + red1[128 + r]) * (1.f/256.f);
        }

    #pragma unroll
    for (int mt = 0; mt < 2; mt++)
        #pragma unroll
        for (int hf = 0; hf < 2; hf++) {
            float m = mean[mt][hf];
            float sq = 0.f;
            #pragma unroll
            for (int nt = 0; nt < 16; nt++) {
                float d0 = c[mt][nt][hf*2] - m;
                float d1 = c[mt][nt][hf*2 + 1] - m;
                sq += d0*d0 + d1*d1;
            }
            sq += __shfl_xor_sync(0xffffffffu, sq, 1);
            sq += __shfl_xor_sync(0xffffffffu, sq, 2);
            if (tig == 0) {
                int r = wm + mt*16 + gid + hf*8;
                red2[(wid & 1)*128 + r] = sq;
            }
        }
    __syncthreads();
    float rstd[2][2];
    #pragma unroll
    for (int mt = 0; mt < 2; mt++)
        #pragma unroll
        for (int hf = 0; hf < 2; hf++) {
            int r = wm + mt*16 + gid + hf*8;
            rstd[mt][hf] = rsqrtf((red2[r] + red2[128 + r]) * (1.f/256.f) + 1e-5f);
        }

    #pragma unroll
    for (int mt = 0; mt < 2; mt++)
        #pragma unroll
        for (int nt = 0; nt < 16; nt++) {
            int col = wn + nt*8 + (tig << 1);
            float2 gg = *(const float2*)(lng + col);
            float2 bb = *(const float2*)(lnb + col);
            #pragma unroll
            for (int hf = 0; hf < 2; hf++) {
                int row = bm + wm + mt*16 + gid + hf*8;
                float m = mean[mt][hf], rs = rstd[mt][hf];
                float v0 = (c[mt][nt][hf*2]     - m) * rs * gg.x + bb.x;
                float v1 = (c[mt][nt][hf*2 + 1] - m) * rs * gg.y + bb.y;
                *(float2*)(out + (size_t)row*256 + col) = make_float2(v0, v1);
            }
        }
}

// ---------------------------------------------------------------------------
// Attention v2: occupancy-2 (112 KB smem). One block per (seq, head).
// smem: PW [256][36] (W in rows 0..95 during projection; per-warp P after),
//       K [256][36], V [256][40]. Q lives in registers (shfl-converted from
//       projection accumulators). A-fragments for projection read global h.
// ---------------------------------------------------------------------------
#define ZP 36
#define VP 40
#define ATTN2_SMEM ((2*256*ZP + 256*VP) * 4)

__global__ __launch_bounds__(256, 2) void k_attn_tc2(
    const float* __restrict__ h, const float* __restrict__ Wq,
    const float* __restrict__ Wk, const float* __restrict__ Wv,
    float* __restrict__ out)
{
    int s  = blockIdx.x;
    int hh = blockIdx.y;
    extern __shared__ float sma[];
    float* PW = sma;                 // [256][36]: W rows 0..95, then per-warp P
    float* Ks = sma + 256*ZP;        // [256][36]
    float* Vs = sma + 2*256*ZP;      // [256][40]

    int tid  = threadIdx.x;
    int lane = tid & 31;
    int wid  = tid >> 5;
    int gid  = lane >> 2, tig = lane & 3;
    int m0   = wid * 32;

    // stage W into PW rows 0..95 (pad 36)
    for (int i = tid; i < 1024; i += 256) {
        int r = i >> 5, c2 = i & 31;
        PW[r*36 + c2]        = Wq[i];
        PW[(32 + r)*36 + c2] = Wk[i];
        PW[(64 + r)*36 + c2] = Wv[i];
    }
    __syncthreads();

    // --- projection: A-frags from global h, W-frags from smem ---
    float qf[2][4][4];               // Q as S-phase A-fragments (registers)
    {
        float aq[2][4][4], ak[2][4][4], av[2][4][4];
        #pragma unroll
        for (int mt = 0; mt < 2; mt++)
            #pragma unroll
            for (int nt = 0; nt < 4; nt++)
                #pragma unroll
                for (int i = 0; i < 4; i++) { aq[mt][nt][i]=0.f; ak[mt][nt][i]=0.f; av[mt][nt][i]=0.f; }

        const float* hb = h + ((size_t)s*TLEN)*FDIM + hh*HDIM;
        #pragma unroll
        for (int ks = 0; ks < 4; ks++) {
            int k0 = ks * 8;
            unsigned int a[2][4];
            #pragma unroll
            for (int mt = 0; mt < 2; mt++) {
                int mr = m0 + mt*16 + gid;
                a[mt][0] = __float_as_uint(hb[(size_t)mr*FDIM + k0 + tig]);
                a[mt][1] = __float_as_uint(hb[(size_t)(mr+8)*FDIM + k0 + tig]);
                a[mt][2] = __float_as_uint(hb[(size_t)mr*FDIM + k0 + tig + 4]);
                a[mt][3] = __float_as_uint(hb[(size_t)(mr+8)*FDIM + k0 + tig + 4]);
            }
            #pragma unroll
            for (int nt = 0; nt < 4; nt++) {
                int nc = nt*8 + gid;
                unsigned int bq0 = __float_as_uint(PW[nc*36 + k0 + tig]);
                unsigned int bq1 = __float_as_uint(PW[nc*36 + k0 + tig + 4]);
                unsigned int bk0 = __float_as_uint(PW[(32+nc)*36 + k0 + tig]);
                unsigned int bk1 = __float_as_uint(PW[(32+nc)*36 + k0 + tig + 4]);
                unsigned int bv0 = __float_as_uint(PW[(64+nc)*36 + k0 + tig]);
                unsigned int bv1 = __float_as_uint(PW[(64+nc)*36 + k0 + tig + 4]);
                #pragma unroll
                for (int mt = 0; mt < 2; mt++) {
                    MMA_TF32(aq[mt][nt], a[mt][0], a[mt][1], a[mt][2], a[mt][3], bq0, bq1);
                    MMA_TF32(ak[mt][nt], a[mt][0], a[mt][1], a[mt][2], a[mt][3], bk0, bk1);
                    MMA_TF32(av[mt][nt], a[mt][0], a[mt][1], a[mt][2], a[mt][3], bv0, bv1);
                }
            }
        }

        // barrier: everyone done reading W from PW before P-region reuse;
        // K/V stores happen after this so no store/read hazard with W.
        __syncthreads();

        // store K, V to smem (accumulator layout -> [row][col])
        #pragma unroll
        for (int mt = 0; mt < 2; mt++)
            #pragma unroll
            for (int nt = 0; nt < 4; nt++) {
                int col = nt*8 + tig*2;
                #pragma unroll
                for (int hf = 0; hf < 2; hf++) {
                    int row = m0 + mt*16 + gid + hf*8;
                    *(float2*)&Ks[row*ZP + col] = make_float2(ak[mt][nt][hf*2], ak[mt][nt][hf*2+1]);
                    *(float2*)&Vs[row*VP + col] = make_float2(av[mt][nt][hf*2], av[mt][nt][hf*2+1]);
                }
            }

        // convert Q accumulators -> A-fragments (cols {2t,2t+1} -> {t,t+4})
        int lo = tig & 1;
        int src0 = (lane & ~3) | (tig >> 1);
        int src1 = src0 + 2;
        #pragma unroll
        for (int mt = 0; mt < 2; mt++)
            #pragma unroll
            for (int ks = 0; ks < 4; ks++) {
                float s0 = __shfl_sync(0xffffffffu, aq[mt][ks][0], src0);
                float s1 = __shfl_sync(0xffffffffu, aq[mt][ks][1], src0);
                float s2 = __shfl_sync(0xffffffffu, aq[mt][ks][2], src0);
                float s3 = __shfl_sync(0xffffffffu, aq[mt][ks][3], src0);
                float t0 = __shfl_sync(0xffffffffu, aq[mt][ks][0], src1);
                float t1 = __shfl_sync(0xffffffffu, aq[mt][ks][1], src1);
                float t2 = __shfl_sync(0xffffffffu, aq[mt][ks][2], src1);
                float t3 = __shfl_sync(0xffffffffu, aq[mt][ks][3], src1);
                qf[mt][ks][0] = lo ? s1 : s0;
                qf[mt][ks][1] = lo ? s3 : s2;
                qf[mt][ks][2] = lo ? t1 : t0;
                qf[mt][ks][3] = lo ? t3 : t2;
            }
    }
    __syncthreads();   // K/V visible to all warps

    // --- S / PV loop ---
    float* Pw = PW + m0*ZP;          // per-warp [32][36]
    float o_acc[2][4][4];
    float lsum[2][2];
    #pragma unroll
    for (int mt = 0; mt < 2; mt++) {
        lsum[mt][0] = 0.f; lsum[mt][1] = 0.f;
        #pragma unroll
        for (int nt = 0; nt < 4; nt++)
            #pragma unroll
            for (int i = 0; i < 4; i++) o_acc[mt][nt][i] = 0.f;
    }

    for (int jc = 0; jc < 4; jc++) {
        // S phase in two nt-halves (register pressure)
        #pragma unroll
        for (int jh = 0; jh < 2; jh++) {
            float s_acc[2][4][4];
            #pragma unroll
            for (int mt = 0; mt < 2; mt++)
                #pragma unroll
                for (int nt = 0; nt < 4; nt++)
                    #pragma unroll
                    for (int i = 0; i < 4; i++) s_acc[mt][nt][i] = 0.f;

            #pragma unroll
            for (int ks = 0; ks < 4; ks++) {
                int k0 = ks * 8;
                #pragma unroll
                for (int nt = 0; nt < 4; nt++) {
                    int nc = jc*64 + jh*32 + nt*8 + gid;
                    unsigned int b0 = __float_as_uint(Ks[nc*ZP + k0 + tig]);
                    unsigned int b1 = __float_as_uint(Ks[nc*ZP + k0 + tig + 4]);
                    #pragma unroll
                    for (int mt = 0; mt < 2; mt++)
                        MMA_TF32(s_acc[mt][nt],
                                 __float_as_uint(qf[mt][ks][0]), __float_as_uint(qf[mt][ks][1]),
                                 __float_as_uint(qf[mt][ks][2]), __float_as_uint(qf[mt][ks][3]),
                                 b0, b1);
                }
            }
            #pragma unroll
            for (int mt = 0; mt < 2; mt++)
                #pragma unroll
                for (int nt = 0; nt < 4; nt++) {
                    float p0 = __expf(s_acc[mt][nt][0] * 0.0625f);
                    float p1 = __expf(s_acc[mt][nt][1] * 0.0625f);
                    float p2 = __expf(s_acc[mt][nt][2] * 0.0625f);
                    float p3 = __expf(s_acc[mt][nt][3] * 0.0625f);
                    lsum[mt][0] += p0 + p1;
                    lsum[mt][1] += p2 + p3;
                    int col = jh*32 + nt*8 + tig*2;
                    int lm = mt*16 + gid;
                    *(float2*)&Pw[lm*ZP + col]     = make_float2(p0, p1);
                    *(float2*)&Pw[(lm+8)*ZP + col] = make_float2(p2, p3);
                }
        }
        __syncwarp();

        // O += P (32x64) @ V chunk (64x32)
        #pragma unroll
        for (int ks = 0; ks < 8; ks++) {
            int k0 = ks * 8;
            unsigned int a[2][4];
            #pragma unroll
            for (int mt = 0; mt < 2; mt++) {
                int lm = mt*16 + gid;
                a[mt][0] = __float_as_uint(Pw[lm*ZP + k0 + tig]);
                a[mt][1] = __float_as_uint(Pw[(lm+8)*ZP + k0 + tig]);
                a[mt][2] = __float_as_uint(Pw[lm*ZP + k0 + tig + 4]);
                a[mt][3] = __float_as_uint(Pw[(lm+8)*ZP + k0 + tig + 4]);
            }
            #pragma unroll
            for (int nt = 0; nt < 4; nt++) {
                int nc = nt*8 + gid;
                unsigned int b0 = __float_as_uint(Vs[(jc*64 + k0 + tig)*VP + nc]);
                unsigned int b1 = __float_as_uint(Vs[(jc*64 + k0 + tig + 4)*VP + nc]);
                #pragma unroll
                for (int mt = 0; mt < 2; mt++)
                    MMA_TF32(o_acc[mt][nt], a[mt][0], a[mt][1], a[mt][2], a[mt][3], b0, b1);
            }
        }
        __syncwarp();
    }

    float inv[2][2];
    #pragma unroll
    for (int mt = 0; mt < 2; mt++)
        #pragma unroll
        for (int hf = 0; hf < 2; hf++) {
            float l = lsum[mt][hf];
            l += __shfl_xor_sync(0xffffffffu, l, 1);
            l += __shfl_xor_sync(0xffffffffu, l, 2);
            inv[mt][hf] = 1.f / l;
        }
    #pragma unroll
    for (int mt = 0; mt < 2; mt++)
        #pragma unroll
        for (int nt = 0; nt < 4; nt++) {
            int col = nt*8 + tig*2;
            #pragma unroll
            for (int hf = 0; hf < 2; hf++) {
                int row = m0 + mt*16 + gid + hf*8;
                float v0 = o_acc[mt][nt][hf*2]   * inv[mt][hf];
                float v1 = o_acc[mt][nt][hf*2+1] * inv[mt][hf];
                *(float2*)(out + ((size_t)s*TLEN + row)*FDIM + hh*HDIM + col) = make_float2(v0, v1);
            }
        }
}

// ---------------------------------------------------------------------------
// Pack with smem transpose
// ---------------------------------------------------------------------------
__global__ __launch_bounds__(256) void k_pack2(
    const float* __restrict__ h, float* __restrict__ flat)
{
    __shared__ float sm[4][260];
    int t = blockIdx.x;
    int n = blockIdx.y;
    int tid = threadIdx.x;

    #pragma unroll
    for (int c = 0; c < 4; c++)
        sm[c][tid] = h[((size_t)(c*16 + n)*256 + t)*256 + tid];
    __syncthreads();

    float* dst = flat + (size_t)n*DFLAT + t*1024;
    #pragma unroll
    for (int j = 0; j < 4; j++) {
        int i = j*256 + tid;
        dst[i] = sm[i & 3][i >> 2];
    }
}

// ---------------------------------------------------------------------------
// Head stage 1 via tf32 mma with 3-term fp32-emulation split.
// ---------------------------------------------------------------------------
#define HM_AP 36
#define HM_ASZ (256*HM_AP)
#define HM_BSZ (16*HM_AP)
#define HM_SMEM ((2*(HM_ASZ + HM_BSZ))*4)

__global__ __launch_bounds__(256, 1) void k_head1_mma(
    const float* __restrict__ eW1, const float* __restrict__ aW1,
    const float* __restrict__ flat, float* __restrict__ z1p)
{
    int kc = blockIdx.x;
    int jb = blockIdx.y;
    const float* W = jb ? aW1 : eW1;
    extern __shared__ float smh[];
    float* Asm = smh;
    float* Bsm = smh + 2*HM_ASZ;
    int tid = threadIdx.x;
    int lane = tid & 31;
    int wid  = tid >> 5;
    int gid  = lane >> 2, tig = lane & 3;
    int m0 = wid * 32;
    size_t kbase = (size_t)kc * 4096;

    auto issue = [&](int st, int kb) {
        float* as = Asm + st*HM_ASZ;
        const float* Wb = W + kbase + kb*32;
        #pragma unroll
        for (int i = 0; i < 8; i++) {
            int idx = i*256 + tid;
            int r = idx >> 3, kq = (idx & 7) << 2;
            cpasync16(as + r*HM_AP + kq, Wb + (size_t)r*DFLAT + kq);
        }
        if (tid < 128) {
            float* bs = Bsm + st*HM_BSZ;
            int r = tid >> 3, kq = (tid & 7) << 2;
            cpasync16(bs + r*HM_AP + kq, flat + (size_t)r*DFLAT + kbase + kb*32 + kq);
        }
        asm volatile("cp.async.commit_group;\n");
    };

    float c[2][2][4];
    #pragma unroll
    for (int mt = 0; mt < 2; mt++)
        #pragma unroll
        for (int nt = 0; nt < 2; nt++)
            #pragma unroll
            for (int i = 0; i < 4; i++) c[mt][nt][i] = 0.f;

    issue(0, 0);
    for (int kb = 0; kb < 128; kb++) {
        int st = kb & 1;
        if (kb + 1 < 128) {
            issue(st ^ 1, kb + 1);
            asm volatile("cp.async.wait_group 1;\n");
        } else {
            asm volatile("cp.async.wait_group 0;\n");
        }
        __syncthreads();

        const float* as = Asm + st*HM_ASZ;
        const float* bs = Bsm + st*HM_BSZ;
        #pragma unroll
        for (int ks = 0; ks < 4; ks++) {
            int k0 = ks * 8;
            float af[2][4];
            unsigned int ahi[2][4], alo[2][4];
            #pragma unroll
            for (int mt = 0; mt < 2; mt++) {
                int mr = m0 + mt*16 + gid;
                af[mt][0] = as[mr*HM_AP + k0 + tig];
                af[mt][1] = as[(mr+8)*HM_AP + k0 + tig];
                af[mt][2] = as[mr*HM_AP + k0 + tig + 4];
                af[mt][3] = as[(mr+8)*HM_AP + k0 + tig + 4];
                #pragma unroll
                for (int i = 0; i < 4; i++) {
                    ahi[mt][i] = tf32_hi(af[mt][i]);
                    alo[mt][i] = __float_as_uint(af[mt][i] - __uint_as_float(ahi[mt][i]));
                }
            }
            #pragma unroll
            for (int nt = 0; nt < 2; nt++) {
                int nc = nt*8 + gid;
                float bf0 = bs[nc*HM_AP + k0 + tig];
                float bf1 = bs[nc*HM_AP + k0 + tig + 4];
                unsigned int bhi0 = tf32_hi(bf0), bhi1 = tf32_hi(bf1);
                unsigned int blo0 = __float_as_uint(bf0 - __uint_as_float(bhi0));
                unsigned int blo1 = __float_as_uint(bf1 - __uint_as_float(bhi1));
                #pragma unroll
                for (int mt = 0; mt < 2; mt++) {
                    MMA_TF32(c[mt][nt], ahi[mt][0], ahi[mt][1], ahi[mt][2], ahi[mt][3], bhi0, bhi1);
                    MMA_TF32(c[mt][nt], ahi[mt][0], ahi[mt][1], ahi[mt][2], ahi[mt][3], blo0, blo1);
                    MMA_TF32(c[mt][nt], alo[mt][0], alo[mt][1], alo[mt][2], alo[mt][3], bhi0, bhi1);
                }
            }
        }
        __syncthreads();
    }

    #pragma unroll
    for (int mt = 0; mt < 2; mt++)
        #pragma unroll
        for (int nt = 0; nt < 2; nt++) {
            int col = nt*8 + tig*2;
            #pragma unroll
            for (int hf = 0; hf < 2; hf++) {
                int row = m0 + mt*16 + gid + hf*8;
                int j = jb*256 + row;
                z1p[((size_t)j*16 + col    )*64 + kc] = c[mt][nt][hf*2];
                z1p[((size_t)j*16 + col + 1)*64 + kc] = c[mt][nt][hf*2 + 1];
            }
        }
}

__global__ void k_hred(const float* __restrict__ z1p, float* __restrict__ z1) {
    int idx = blockIdx.x * 256 + threadIdx.x;
    float s = 0.f;
    const float* p = z1p + (size_t)idx * 64;
    #pragma unroll 8
    for (int i = 0; i < 64; i++) s += p[i];
    z1[idx] = s;
}

// ---------------------------------------------------------------------------
// Head stage 2
// ---------------------------------------------------------------------------
__global__ __launch_bounds__(256) void k_head2(
    const float* __restrict__ z1,
    const float* __restrict__ eb1, const float* __restrict__ eg,
    const float* __restrict__ ebt, const float* __restrict__ eW2,
    const float* __restrict__ eb2, const float* __restrict__ eW3,
    const float* __restrict__ eb3, const float* __restrict__ eW4,
    const float* __restrict__ ab1, const float* __restrict__ ag,
    const float* __restrict__ abt, const float* __restrict__ aW2,
    const float* __restrict__ ab2, const float* __restrict__ aW3,
    const float* __restrict__ ab3, const float* __restrict__ aW4,
    float* __restrict__ out)
{
    int head = blockIdx.x;
    const float* b1 = head ? ab1 : eb1;
    const float* gg = head ? ag  : eg;
    const float* bt = head ? abt : ebt;
    const float* W2 = head ? aW2 : eW2;
    const float* b2 = head ? ab2 : eb2;
    const float* W3 = head ? aW3 : eW3;
    const float* b3 = head ? ab3 : eb3;
    const float* W4 = head ? aW4 : eW4;

    __shared__ float zs[256*17];
    int j = threadIdx.x;
    const float ibn = rsqrtf(1.f + 1e-5f);

    #pragma unroll
    for (int n = 0; n < 16; n++) {
        float v = z1[(size_t)(head*256 + j)*16 + n];
        v = (v + b1[j]) * ibn * gg[j] + bt[j];
        zs[j*17 + n] = fmaxf(v, 0.f);
    }
    __syncthreads();

    float acc[16];
    #pragma unroll
    for (int n = 0; n < 16; n++) acc[n] = b2[j];
    for (int k = 0; k < 256; k++) {
        float w = W2[j*256 + k];
        #pragma unroll
        for (int n = 0; n < 16; n++) acc[n] += w * zs[k*17 + n];
    }
    __syncthreads();
    #pragma unroll
    for (int n = 0; n < 16; n++) zs[j*17 + n] = fmaxf(acc[n], 0.f);
    __syncthreads();

    #pragma unroll
    for (int n = 0; n < 16; n++) acc[n] = b3[j];
    for (int k = 0; k < 256; k++) {
        float w = W3[j*256 + k];
        #pragma unroll
        for (int n = 0; n < 16; n++) acc[n] += w * zs[k*17 + n];
    }
    __syncthreads();
    #pragma unroll
    for (int n = 0; n < 16; n++) zs[j*17 + n] = fmaxf(acc[n], 0.f);
    __syncthreads();

    if (j < 32) {
        int i = j & 1, n = j >> 1;
        float a4 = 0.f;
        for (int k = 0; k < 256; k++) a4 += W4[i*256 + k] * zs[k*17 + n];
        float lo = head ? 0.f          : -0.78539818525f;
        float hi = head ? 6.28318548202f : 1.57079637050f;
        a4 = fminf(fmaxf(a4, lo), hi);
        out[n*4 + i*2 + head] = a4;
    }
}

// ---------------------------------------------------------------------------
// Host launcher
// ---------------------------------------------------------------------------
static float* symaddr(const void* sym) {
    void* p = nullptr;
    cudaGetSymbolAddress(&p, sym);
    return (float*)p;
}

extern "C" void kernel_launch(void* const* d_in, const int* in_sizes, int n_in,
                              void* d_out, int out_size)
{
    const float* x    = (const float*)d_in[0];
    const float* Wq   = (const float*)d_in[1];
    const float* Wk   = (const float*)d_in[2];
    const float* Wv   = (const float*)d_in[3];
    const float* Wo   = (const float*)d_in[4];
    const float* bo   = (const float*)d_in[5];
    const float* ln1g = (const float*)d_in[6];
    const float* ln1b = (const float*)d_in[7];
    const float* ln2g = (const float*)d_in[8];
    const float* ln2b = (const float*)d_in[9];
    const float* ffW1 = (const float*)d_in[10];
    const float* ffb1 = (const float*)d_in[11];
    const float* ffW2 = (const float*)d_in[12];
    const float* ffb2 = (const float*)d_in[13];
    const float* eW1  = (const float*)d_in[14];
    const float* eb1  = (const float*)d_in[15];
    const float* eg   = (const float*)d_in[16];
    const float* ebt  = (const float*)d_in[17];
    const float* eW2  = (const float*)d_in[18];
    const float* eb2  = (const float*)d_in[19];
    const float* eW3  = (const float*)d_in[20];
    const float* eb3  = (const float*)d_in[21];
    const float* eW4  = (const float*)d_in[22];
    const float* aW1  = (const float*)d_in[23];
    const float* ab1  = (const float*)d_in[24];
    const float* ag   = (const float*)d_in[25];
    const float* abt  = (const float*)d_in[26];
    const float* aW2  = (const float*)d_in[27];
    const float* ab2  = (const float*)d_in[28];
    const float* aW3  = (const float*)d_in[29];
    const float* ab3  = (const float*)d_in[30];
    const float* aW4  = (const float*)d_in[31];
    float* out = (float*)d_out;

    float* ph    = symaddr(g_h);
    float* pattn = symaddr(g_attn);
    float* px1   = symaddr(g_x1);
    float* pff   = symaddr(g_ff);
    float* pflat = symaddr(g_flat);
    float* pz1p  = symaddr(g_z1p);
    float* pz1   = symaddr(g_z1);

    cudaFuncSetAttribute(k_attn_tc2,  cudaFuncAttributeMaxDynamicSharedMemorySize, ATTN2_SMEM);
    cudaFuncSetAttribute(k_gemm_tc2,  cudaFuncAttributeMaxDynamicSharedMemorySize, G2_SMEM);
    cudaFuncSetAttribute(k_gemm_ln,   cudaFuncAttributeMaxDynamicSharedMemorySize, GL_SMEM);
    cudaFuncSetAttribute(k_head1_mma, cudaFuncAttributeMaxDynamicSharedMemorySize, HM_SMEM);

    k_embed2<<<dim3(8, 8, 16), 256>>>(x, ph);

    for (int l = 0; l < NLAYER; l++) {
        k_attn_tc2<<<dim3(SEQ, NHEAD), 256, ATTN2_SMEM>>>(
            ph, Wq + l*1024, Wk + l*1024, Wv + l*1024, pattn);
        k_gemm_ln<<<MROWS/128, 256, GL_SMEM>>>(
            pattn, Wo + l*65536, bo + l*256, ph,
            ln1g + l*256, ln1b + l*256, px1, FDIM);
        k_gemm_tc2<<<dim3(MROWS/256, EDIM/128), 256, G2_SMEM>>>(
            px1, ffW1 + l*(EDIM*FDIM), ffb1 + l*EDIM, pff, EDIM, FDIM);
        k_gemm_ln<<<MROWS/128, 256, GL_SMEM>>>(
            pff, ffW2 + l*(FDIM*EDIM), ffb2 + l*256, px1,
            ln2g + l*256, ln2b + l*256, ph, EDIM);
    }

    k_pack2<<<dim3(TLEN, NB), 256>>>(ph, pflat);
    k_head1_mma<<<dim3(64, 2), 256, HM_SMEM>>>(eW1, aW1, pflat, pz1p);
    k_hred<<<32, 256>>>(pz1p, pz1);
    k_head2<<<2, 256>>>(pz1,
                        eb1, eg, ebt, eW2, eb2, eW3, eb3, eW4,
                        ab1, ag, abt, aW2, ab2, aW3, ab3, aW4,
                        out);
}